// round 13
// baseline (speedup 1.0000x reference)
#include <cuda_runtime.h>
#include <cuda_fp16.h>
#include <math.h>
#include <stdint.h>

#define Bz 8
#define Sz 4096
#define Dz 512
#define Mz (Bz * Sz)          // 32768 rows
#define D4 (4 * Dz)           // 2048
#define D2 (2 * Dz)           // 1024

#define SCH 64                // scan chunks
#define SLEN (Sz / SCH)       // 64 steps per chunk
#define NCHAN (Bz * Dz)       // 4096 channels

// ---------------------------------------------------------------------------
// Scratch (static device globals; no allocation)
// ---------------------------------------------------------------------------
// scan inputs, fp16 row-major [Mz, Dz]
__device__ __half g_omega[(size_t)Mz * Dz];
__device__ __half g_mag  [(size_t)Mz * Dz];
__device__ __half g_gate [(size_t)Mz * Dz];
__device__ __half g_qoff [(size_t)Mz * Dz];
__device__ __half g_phii [(size_t)Mz * Dz];

// scan chunk statistics [chunk][channel]
__device__ float g_sphi[SCH * NCHAN];
__device__ float g_sm  [SCH * NCHAN];
__device__ float g_smr [SCH * NCHAN];
__device__ float g_smi [SCH * NCHAN];

// packed fp16 activations (SW128 tile-blocked)
__device__ __half g_xp  [(size_t)Mz * Dz];
__device__ __half g_p1p [(size_t)Mz * Dz];
__device__ __half g_ctxp[(size_t)Mz * D4];
__device__ __half g_hp  [(size_t)Mz * D2];

// fp16 weights (transposed to [N,K], SW128 tile-blocked)
__device__ __half g_wcat[5 * Dz * Dz];          // [omega|mag|gate|qoff|p1]
__device__ __half g_wp2[Dz * Dz];
__device__ __half g_wo1[(size_t)D4 * D2];
__device__ __half g_wo2[D2 * Dz];

// ---------------------------------------------------------------------------
// PTX helpers
// ---------------------------------------------------------------------------
__device__ __forceinline__ uint32_t smem_u32(const void* p) {
    uint32_t a;
    asm("{ .reg .u64 t; cvta.to.shared.u64 t, %1; cvt.u32.u64 %0, t; }" : "=r"(a) : "l"(p));
    return a;
}

__device__ __forceinline__ void cp16(uint32_t dst, const void* src) {
    asm volatile("cp.async.cg.shared.global [%0], [%1], 16;" :: "r"(dst), "l"(src));
}
#define CP_COMMIT() asm volatile("cp.async.commit_group;" ::: "memory")
#define CP_WAIT(n)  asm volatile("cp.async.wait_group %0;" :: "n"(n) : "memory")

__device__ __forceinline__ void ldsm4(uint32_t* r, uint32_t addr) {
    asm volatile("ldmatrix.sync.aligned.m8n8.x4.shared.b16 {%0,%1,%2,%3}, [%4];"
                 : "=r"(r[0]), "=r"(r[1]), "=r"(r[2]), "=r"(r[3]) : "r"(addr));
}

__device__ __forceinline__ void mma16816(float* d, const uint32_t* a, uint32_t b0, uint32_t b1) {
    asm volatile(
        "mma.sync.aligned.m16n8k16.row.col.f32.f16.f16.f32 "
        "{%0,%1,%2,%3}, {%4,%5,%6,%7}, {%8,%9}, {%0,%1,%2,%3};"
        : "+f"(d[0]), "+f"(d[1]), "+f"(d[2]), "+f"(d[3])
        : "r"(a[0]), "r"(a[1]), "r"(a[2]), "r"(a[3]), "r"(b0), "r"(b1));
}

__device__ __forceinline__ uint32_t sw128(uint32_t b) { return b ^ ((b >> 3) & 0x70); }

// read a float2 (2 fp16) from the SW128 tile-blocked layout at (row, d0)
__device__ __forceinline__ float2 ldxp2(const __half* xp, int row, int d0, int nkc) {
    size_t blk = (size_t)(row >> 7) * nkc + (d0 >> 6);
    uint32_t sw = sw128((uint32_t)((row & 127) * 128 + (d0 & 63) * 2));
    return __half22float2(*(const __half2*)((const char*)xp + blk * 16384 + sw));
}

// ---------------------------------------------------------------------------
// Packing kernels
// ---------------------------------------------------------------------------
__global__ void pack_a_kernel(const float* __restrict__ A,
                              __half* __restrict__ P,
                              int K, long total8)
{
    long idx = (long)blockIdx.x * blockDim.x + threadIdx.x;
    if (idx >= total8) return;
    int kk8 = K >> 3;
    int row = (int)(idx / kk8);
    int k   = (int)(idx % kk8) << 3;

    const float4* p = (const float4*)(A + (size_t)row * K + k);
    float4 a = p[0], b = p[1];
    float v[8] = {a.x, a.y, a.z, a.w, b.x, b.y, b.z, b.w};

    __align__(16) __half h[8];
#pragma unroll
    for (int i = 0; i < 8; i++) h[i] = __float2half(v[i]);

    int mt = row >> 7, r = row & 127, ch = k >> 6, c = k & 63;
    size_t blk = (size_t)mt * (K >> 6) + ch;
    uint32_t sw = sw128((uint32_t)(r * 128 + c * 2));
    size_t off = blk * 16384 + sw;
    *(uint4*)((char*)P + off) = *(const uint4*)h;
}

__global__ void pack_w_kernel(const float* __restrict__ W,
                              __half* __restrict__ P,
                              int K, int N)
{
    long idx = (long)blockIdx.x * blockDim.x + threadIdx.x;
    long total = (long)N * (K >> 3);
    if (idx >= total) return;
    int n  = (int)(idx % N);
    int kg = (int)(idx / N);
    int k  = kg << 3;

    __align__(16) __half h[8];
#pragma unroll
    for (int i = 0; i < 8; i++) h[i] = __float2half(W[(size_t)(k + i) * N + n]);

    int nt = n >> 7, rn = n & 127, ch = k >> 6, c = k & 63;
    size_t blk = (size_t)nt * (K >> 6) + ch;
    uint32_t sw = sw128((uint32_t)(rn * 128 + c * 2));
    size_t off = blk * 16384 + sw;
    *(uint4*)((char*)P + off) = *(const uint4*)h;
}

// ---------------------------------------------------------------------------
// MMA core: BM=128, BN=128, BK=64, 256 threads (8 warps: 4 wm x 2 wn),
// warp tile 32x64. Stage = A + B = 32KB. 3-stage pipeline, 2 CTAs/SM.
// ---------------------------------------------------------------------------
#define NSTAGE 3
#define TB 16384
#define STAGE_BYTES (2 * TB)
#define GEMM_SMEM   (NSTAGE * STAGE_BYTES)   // 96KB -> 2 CTAs/SM

__device__ __forceinline__ void mma_chunk(uint32_t sA, uint32_t sB,
                                          int wm, int wn, int lane,
                                          float acc[2][8][4])
{
    const int a_row = lane & 15;
    const int a_kb  = (lane >> 4) * 16;
#pragma unroll
    for (int k16 = 0; k16 < 4; ++k16) {
        const int kb = k16 * 32 + a_kb;
        uint32_t ah[2][4], bh[4][4];
#pragma unroll
        for (int im = 0; im < 2; im++) {
            uint32_t b = (uint32_t)((wm * 32 + im * 16 + a_row) * 128 + kb);
            ldsm4(ah[im], sA + sw128(b));
        }
#pragma unroll
        for (int j2 = 0; j2 < 4; j2++) {
            uint32_t b = (uint32_t)((wn * 64 + j2 * 16 + a_row) * 128 + kb);
            ldsm4(bh[j2], sB + sw128(b));
        }
#pragma unroll
        for (int im = 0; im < 2; im++)
#pragma unroll
            for (int jn = 0; jn < 8; jn++) {
                const int j2 = jn >> 1, jo = jn & 1;
                mma16816(acc[im][jn], ah[im], bh[j2][jo], bh[j2][2 + jo]);
            }
    }
}

__device__ __forceinline__ float gelu_exact(float v) {
    return 0.5f * v * (1.0f + erff(v * 0.70710678118654752f));
}

__device__ __forceinline__ void copy_stage(uint32_t sdst,
                                           const char* A, const char* B, int tid)
{
#pragma unroll
    for (int j = 0; j < 4; j++) {
        uint32_t o = (uint32_t)tid * 16 + j * 4096;
        cp16(sdst + o,      A + o);
        cp16(sdst + TB + o, B + o);
    }
}

// ---------------------------------------------------------------------------
// Fused projection GEMM: grid (20, 256). group = bx>>2 (0..4), n-tile = bx&3.
// group: 0 omega, 1 mag(sig5), 2 gate(sig), 3 qoff -> fp16 row-major out,
//        4 p1(gelu) -> packed fp16
// ---------------------------------------------------------------------------
__global__ __launch_bounds__(256, 2)
void proj_gemm(const __half* __restrict__ Ap, const __half* __restrict__ W,
               const float* __restrict__ b_om, const float* __restrict__ b_mg,
               const float* __restrict__ b_gt, const float* __restrict__ b_qo,
               const float* __restrict__ b_p1,
               __half* __restrict__ c_om, __half* __restrict__ c_mg,
               __half* __restrict__ c_gt, __half* __restrict__ c_qo,
               __half* __restrict__ p1p)
{
    extern __shared__ __align__(1024) char dsmem[];
    const uint32_t sbase = smem_u32(dsmem);

    const int tid  = threadIdx.x;
    const int wid  = tid >> 5;
    const int lane = tid & 31;
    const int wm   = wid >> 1;      // 0..3 (32 rows each)
    const int wn   = wid & 1;       // 0..1 (64 cols each)

    const int group = blockIdx.x >> 2;
    const int ntile = blockIdx.x & 3;

    const int nch = 8;  // K=512
    const char* srcA = (const char*)Ap + (size_t)blockIdx.y * nch * TB;
    const char* srcB = (const char*)W + ((size_t)group * 4 + ntile) * nch * TB;

    float acc[2][8][4];
#pragma unroll
    for (int i = 0; i < 2; i++)
#pragma unroll
        for (int j = 0; j < 8; j++)
#pragma unroll
            for (int q = 0; q < 4; q++) acc[i][j][q] = 0.f;

#pragma unroll
    for (int c = 0; c < NSTAGE - 1; c++) {
        if (c < nch)
            copy_stage(sbase + c * STAGE_BYTES, srcA + (size_t)c * TB, srcB + (size_t)c * TB, tid);
        CP_COMMIT();
    }

    for (int ch = 0; ch < nch; ++ch) {
        CP_WAIT(NSTAGE - 2);
        __syncthreads();
        const int pc = ch + NSTAGE - 1;
        if (pc < nch)
            copy_stage(sbase + (pc % NSTAGE) * STAGE_BYTES,
                       srcA + (size_t)pc * TB, srcB + (size_t)pc * TB, tid);
        CP_COMMIT();

        const uint32_t sA = sbase + (ch % NSTAGE) * STAGE_BYTES;
        mma_chunk(sA, sA + TB, wm, wn, lane, acc);
        __syncthreads();
    }

    // ---------------- epilogue ----------------
    const float* bias = (group == 0) ? b_om : (group == 1) ? b_mg :
                        (group == 2) ? b_gt : (group == 3) ? b_qo : b_p1;
    __half* cout = (group == 0) ? c_om : (group == 1) ? c_mg :
                   (group == 2) ? c_gt : c_qo;

    const int m0  = blockIdx.y * 128 + wm * 32 + (lane >> 2);
    const int nl0 = ntile * 128 + wn * 64 + (lane & 3) * 2;

#pragma unroll
    for (int im = 0; im < 2; im++) {
#pragma unroll
        for (int half = 0; half < 2; half++) {
            const int row = m0 + im * 16 + half * 8;
#pragma unroll
            for (int jn = 0; jn < 8; jn++) {
                const int col = nl0 + jn * 8;   // 0..511 within group
                float v0 = acc[im][jn][half * 2 + 0] + bias[col];
                float v1 = acc[im][jn][half * 2 + 1] + bias[col + 1];
                if (group == 1) { v0 = 5.f / (1.f + expf(-v0)); v1 = 5.f / (1.f + expf(-v1)); }
                else if (group == 2) { v0 = 1.f / (1.f + expf(-v0)); v1 = 1.f / (1.f + expf(-v1)); }
                else if (group == 4) { v0 = gelu_exact(v0); v1 = gelu_exact(v1); }

                __half h0 = __float2half(v0);
                __half h1 = __float2half(v1);
                uint32_t hp = ((uint32_t)__half_as_ushort(h1) << 16) | __half_as_ushort(h0);
                if (group == 4) {
                    size_t blk = (size_t)(row >> 7) * 8 + (col >> 6);
                    uint32_t sw = sw128((uint32_t)((row & 127) * 128 + (col & 63) * 2));
                    size_t off = blk * 16384 + sw;
                    *(uint32_t*)((char*)p1p + off) = hp;
                } else {
                    *(uint32_t*)(cout + (size_t)row * Dz + col) = hp;
                }
            }
        }
    }
}

// ---------------------------------------------------------------------------
// generic GEMM: EPI 0 none, 1 gelu, 4 +resid.
// OUT: 0 = fp32 C, 1 = packed fp16 (SW128 blocked), 2 = fp16 row-major
// grid (N/128, M/128)
// ---------------------------------------------------------------------------
template <int EPI, int OUT>
__global__ __launch_bounds__(256, 2)
void gemm_mma(const __half* __restrict__ Ap, const __half* __restrict__ Bp,
              const float* __restrict__ bias, float* __restrict__ C,
              __half* __restrict__ Hout,
              const float* __restrict__ resid, int N, int K)
{
    extern __shared__ __align__(1024) char dsmem[];
    const uint32_t sbase = smem_u32(dsmem);

    const int tid  = threadIdx.x;
    const int wid  = tid >> 5;
    const int lane = tid & 31;
    const int wm   = wid >> 1;
    const int wn   = wid & 1;

    const int nch = K >> 6;
    const char* srcA = (const char*)Ap + (size_t)blockIdx.y * nch * TB;
    const char* srcB = (const char*)Bp + (size_t)blockIdx.x * nch * TB;

    float acc[2][8][4];
#pragma unroll
    for (int i = 0; i < 2; i++)
#pragma unroll
        for (int j = 0; j < 8; j++)
#pragma unroll
            for (int q = 0; q < 4; q++) acc[i][j][q] = 0.f;

#pragma unroll
    for (int c = 0; c < NSTAGE - 1; c++) {
        if (c < nch)
            copy_stage(sbase + c * STAGE_BYTES, srcA + (size_t)c * TB, srcB + (size_t)c * TB, tid);
        CP_COMMIT();
    }

    for (int ch = 0; ch < nch; ++ch) {
        CP_WAIT(NSTAGE - 2);
        __syncthreads();
        const int pc = ch + NSTAGE - 1;
        if (pc < nch)
            copy_stage(sbase + (pc % NSTAGE) * STAGE_BYTES,
                       srcA + (size_t)pc * TB, srcB + (size_t)pc * TB, tid);
        CP_COMMIT();

        const uint32_t sA = sbase + (ch % NSTAGE) * STAGE_BYTES;
        mma_chunk(sA, sA + TB, wm, wn, lane, acc);
        __syncthreads();
    }

    const int m0 = blockIdx.y * 128 + wm * 32 + (lane >> 2);
    const int n0 = blockIdx.x * 128 + wn * 64 + (lane & 3) * 2;
    const int nkc = N >> 6;

#pragma unroll
    for (int im = 0; im < 2; im++) {
#pragma unroll
        for (int half = 0; half < 2; half++) {
            const int row = m0 + im * 16 + half * 8;
            float* crow = (OUT == 0) ? (C + (size_t)row * N) : nullptr;
            const float* rrow = (EPI == 4) ? (resid + (size_t)row * N) : nullptr;
#pragma unroll
            for (int jn = 0; jn < 8; jn++) {
                const int col = n0 + jn * 8;
                float v0 = acc[im][jn][half * 2 + 0] + bias[col];
                float v1 = acc[im][jn][half * 2 + 1] + bias[col + 1];
                if (EPI == 1) { v0 = gelu_exact(v0); v1 = gelu_exact(v1); }
                else if (EPI == 4) { v0 += rrow[col]; v1 += rrow[col + 1]; }

                if (OUT == 0) {
                    *(float2*)(crow + col) = make_float2(v0, v1);
                } else {
                    __half h0 = __float2half(v0);
                    __half h1 = __float2half(v1);
                    uint32_t hp = ((uint32_t)__half_as_ushort(h1) << 16) | __half_as_ushort(h0);
                    if (OUT == 1) {
                        size_t blk = (size_t)(row >> 7) * nkc + (col >> 6);
                        uint32_t sw = sw128((uint32_t)((row & 127) * 128 + (col & 63) * 2));
                        size_t off = blk * 16384 + sw;
                        *(uint32_t*)((char*)Hout + off) = hp;
                    } else {
                        *(uint32_t*)(Hout + (size_t)row * N + col) = hp;
                    }
                }
            }
        }
    }
}

// ---------------------------------------------------------------------------
// Parallel scan (fp16 inputs incl. packed x, fp32 accumulation)
// ---------------------------------------------------------------------------
__device__ __forceinline__ float2 ldh2(const __half* p) {
    return __half22float2(*(const __half2*)p);
}

__global__ __launch_bounds__(256)
void scan_sum1(const float* __restrict__ iscale)
{
    const int chunk = blockIdx.x, b = blockIdx.y;
    const int d0 = threadIdx.x * 2;
    float2 is2 = *(const float2*)(iscale + d0);
    const float i0 = fabsf(is2.x), i1 = fabsf(is2.y);

    size_t idx = ((size_t)b * Sz + (size_t)chunk * SLEN) * Dz + d0;
    float sp0 = 0.f, sp1 = 0.f, sm0 = 0.f, sm1 = 0.f;
#pragma unroll 4
    for (int s = 0; s < SLEN; ++s) {
        float2 g = ldh2(g_gate + idx);
        float2 o = ldh2(g_omega + idx);
        float2 m = ldh2(g_mag + idx);
        sp0 += g.x * o.x * i0;  sp1 += g.y * o.y * i1;
        sm0 += m.x;             sm1 += m.y;
        idx += Dz;
    }
    int ch = b * Dz + d0;
    *(float2*)&g_sphi[chunk * NCHAN + ch] = make_float2(sp0, sp1);
    *(float2*)&g_sm  [chunk * NCHAN + ch] = make_float2(sm0, sm1);
}

__global__ void scan_pfx1()
{
    int ch = blockIdx.x * blockDim.x + threadIdx.x;
    if (ch >= NCHAN) return;
    float rp = 0.f, rm = 0.f;
    for (int c = 0; c < SCH; ++c) {
        int i = c * NCHAN + ch;
        float tp = g_sphi[i]; g_sphi[i] = rp; rp += tp;
        float tm = g_sm[i];   g_sm[i]   = rm; rm += tm;
    }
}

__global__ __launch_bounds__(256)
void scan_sum2(const float* __restrict__ iscale)
{
    const int chunk = blockIdx.x, b = blockIdx.y;
    const int d0 = threadIdx.x * 2;
    float2 is2 = *(const float2*)(iscale + d0);
    const float i0 = fabsf(is2.x), i1 = fabsf(is2.y);
    const int ch = b * Dz + d0;
    float2 phib = *(const float2*)&g_sphi[chunk * NCHAN + ch];

    int row = b * Sz + chunk * SLEN;
    size_t idx = (size_t)row * Dz + d0;
    float pc0 = 0.f, pc1 = 0.f, r0 = 0.f, r1 = 0.f, q0 = 0.f, q1 = 0.f;
#pragma unroll 4
    for (int s = 0; s < SLEN; ++s) {
        float2 g = ldh2(g_gate + idx);
        float2 o = ldh2(g_omega + idx);
        float2 m = ldh2(g_mag + idx);
        float2 xv = ldxp2(g_xp, row + s, d0, 8);
        float2 pv = ldh2(g_phii + idx);
        pc0 += g.x * o.x * i0;
        pc1 += g.y * o.y * i1;
        float c, sn;
        __sincosf(pv.x + phib.x + pc0, &sn, &c);
        float wc = m.x * xv.x;
        r0 += wc * c;  q0 += wc * sn;
        __sincosf(pv.y + phib.y + pc1, &sn, &c);
        wc = m.y * xv.y;
        r1 += wc * c;  q1 += wc * sn;
        idx += Dz;
    }
    *(float2*)&g_smr[chunk * NCHAN + ch] = make_float2(r0, r1);
    *(float2*)&g_smi[chunk * NCHAN + ch] = make_float2(q0, q1);
}

__global__ void scan_pfx2()
{
    int ch = blockIdx.x * blockDim.x + threadIdx.x;
    if (ch >= NCHAN) return;
    float rr = 0.f, ri = 0.f;
    for (int c = 0; c < SCH; ++c) {
        int i = c * NCHAN + ch;
        float tr = g_smr[i]; g_smr[i] = rr; rr += tr;
        float ti = g_smi[i]; g_smi[i] = ri; ri += ti;
    }
}

__device__ __forceinline__ float block_reduce_sum(float val)
{
    __shared__ float sh[8];
    int lane = threadIdx.x & 31, w = threadIdx.x >> 5;
    __syncthreads();
#pragma unroll
    for (int o = 16; o > 0; o >>= 1) val += __shfl_down_sync(0xffffffffu, val, o);
    if (lane == 0) sh[w] = val;
    __syncthreads();
    if (w == 0) {
        val = (lane < 8) ? sh[lane] : 0.f;
#pragma unroll
        for (int o = 4; o > 0; o >>= 1) val += __shfl_down_sync(0xffffffffu, val, o);
        if (lane == 0) sh[0] = val;
    }
    __syncthreads();
    return sh[0];
}

__global__ __launch_bounds__(256)
void scan_final_ln(const float* __restrict__ iscale,
                   const float* __restrict__ gamma, const float* __restrict__ beta,
                   __half* __restrict__ Pctx)
{
    const int chunk = blockIdx.x, b = blockIdx.y;
    const int d0 = threadIdx.x * 2;
    float2 is2 = *(const float2*)(iscale + d0);
    const float i0 = fabsf(is2.x), i1 = fabsf(is2.y);
    const int ch = b * Dz + d0;

    float2 phib = *(const float2*)&g_sphi[chunk * NCHAN + ch];
    float2 mr   = *(const float2*)&g_smr [chunk * NCHAN + ch];
    float2 mi   = *(const float2*)&g_smi [chunk * NCHAN + ch];
    float2 cm   = *(const float2*)&g_sm  [chunk * NCHAN + ch];

    float2 gg[4], bb[4];
#pragma unroll
    for (int j = 0; j < 4; j++) {
        gg[j] = *(const float2*)(gamma + j * Dz + d0);
        bb[j] = *(const float2*)(beta  + j * Dz + d0);
    }

    int row = b * Sz + chunk * SLEN;
    size_t idx = (size_t)row * Dz + d0;
    float pc0 = 0.f, pc1 = 0.f;

    for (int s = 0; s < SLEN; ++s, ++row, idx += Dz) {
        float2 g  = ldh2(g_gate + idx);
        float2 o  = ldh2(g_omega + idx);
        float2 m  = ldh2(g_mag + idx);
        float2 xv = ldxp2(g_xp, row, d0, 8);
        float2 pv = ldh2(g_phii + idx);
        float2 qv = ldh2(g_qoff + idx);

        float v[2][4];
        {
            pc0 += g.x * o.x * i0;
            float phi = pv.x + phib.x + pc0;
            float c, sn; __sincosf(phi, &sn, &c);
            float wc = m.x * xv.x;
            mr.x += wc * c;  mi.x += wc * sn;  cm.x += m.x;
            float r = rsqrtf(cm.x + 1e-8f);
            float mrn = mr.x * r, min_ = mi.x * r;
            float cq, sq; __sincosf(phi + qv.x, &sq, &cq);
            v[0][0] = xv.x * c;  v[0][1] = xv.x * sn;
            v[0][2] = mrn * cq + min_ * sq;  v[0][3] = min_ * cq - mrn * sq;
        }
        {
            pc1 += g.y * o.y * i1;
            float phi = pv.y + phib.y + pc1;
            float c, sn; __sincosf(phi, &sn, &c);
            float wc = m.y * xv.y;
            mr.y += wc * c;  mi.y += wc * sn;  cm.y += m.y;
            float r = rsqrtf(cm.y + 1e-8f);
            float mrn = mr.y * r, min_ = mi.y * r;
            float cq, sq; __sincosf(phi + qv.y, &sq, &cq);
            v[1][0] = xv.y * c;  v[1][1] = xv.y * sn;
            v[1][2] = mrn * cq + min_ * sq;  v[1][3] = min_ * cq - mrn * sq;
        }

        float part = 0.f;
#pragma unroll
        for (int j = 0; j < 4; j++) part += v[0][j] + v[1][j];
        float mean = block_reduce_sum(part) * (1.0f / (float)D4);

        float sqp = 0.f;
#pragma unroll
        for (int j = 0; j < 4; j++) {
            float a0 = v[0][j] - mean, a1 = v[1][j] - mean;
            sqp += a0 * a0 + a1 * a1;
        }
        float rstd = rsqrtf(block_reduce_sum(sqp) * (1.0f / (float)D4) + 1e-5f);

        const size_t blkrow = (size_t)(row >> 7) * (D4 >> 6);
        const uint32_t rsw = (uint32_t)((row & 127) * 128);
#pragma unroll
        for (int j = 0; j < 4; j++) {
            float y0 = (v[0][j] - mean) * rstd * gg[j].x + bb[j].x;
            float y1 = (v[1][j] - mean) * rstd * gg[j].y + bb[j].y;
            __half h0 = __float2half(y0);
            __half h1 = __float2half(y1);
            uint32_t hp = ((uint32_t)__half_as_ushort(h1) << 16) | __half_as_ushort(h0);
            const int col = j * Dz + d0;
            size_t blk = blkrow + (col >> 6);
            uint32_t sw = sw128(rsw + (uint32_t)((col & 63) * 2));
            size_t off = blk * 16384 + sw;
            *(uint32_t*)((char*)Pctx + off) = hp;
        }
    }
}

// ---------------------------------------------------------------------------
// launch
// ---------------------------------------------------------------------------
static inline void* sym(const void* s) { void* p = nullptr; cudaGetSymbolAddress(&p, s); return p; }

extern "C" void kernel_launch(void* const* d_in, const int* in_sizes, int n_in,
                              void* d_out, int out_size)
{
    const float* x       = (const float*)d_in[0];
    const float* W_omega = (const float*)d_in[1];
    const float* b_omega = (const float*)d_in[2];
    const float* W_p1    = (const float*)d_in[3];
    const float* b_p1    = (const float*)d_in[4];
    const float* W_p2    = (const float*)d_in[5];
    const float* b_p2    = (const float*)d_in[6];
    const float* W_gate  = (const float*)d_in[7];
    const float* b_gate  = (const float*)d_in[8];
    const float* iscale  = (const float*)d_in[9];
    const float* W_mag   = (const float*)d_in[10];
    const float* b_mag   = (const float*)d_in[11];
    const float* W_qoff  = (const float*)d_in[12];
    const float* b_qoff  = (const float*)d_in[13];
    const float* ln_g    = (const float*)d_in[14];
    const float* ln_b    = (const float*)d_in[15];
    const float* W_o1    = (const float*)d_in[16];
    const float* b_o1    = (const float*)d_in[17];
    const float* W_o2    = (const float*)d_in[18];
    const float* b_o2    = (const float*)d_in[19];
    float* out = (float*)d_out;

    __half* p_omega = (__half*)sym(g_omega);
    __half* p_mag   = (__half*)sym(g_mag);
    __half* p_gate  = (__half*)sym(g_gate);
    __half* p_qoff  = (__half*)sym(g_qoff);
    __half* p_phii  = (__half*)sym(g_phii);

    __half* xp   = (__half*)sym(g_xp);
    __half* p1p  = (__half*)sym(g_p1p);
    __half* cxp  = (__half*)sym(g_ctxp);
    __half* hp   = (__half*)sym(g_hp);

    __half* wcat = (__half*)sym(g_wcat);
    __half* wp2  = (__half*)sym(g_wp2);
    __half* wo1  = (__half*)sym(g_wo1);
    __half* wo2  = (__half*)sym(g_wo2);

    cudaFuncSetAttribute(proj_gemm,     cudaFuncAttributeMaxDynamicSharedMemorySize, GEMM_SMEM);
    cudaFuncSetAttribute(gemm_mma<0,2>, cudaFuncAttributeMaxDynamicSharedMemorySize, GEMM_SMEM);
    cudaFuncSetAttribute(gemm_mma<1,1>, cudaFuncAttributeMaxDynamicSharedMemorySize, GEMM_SMEM);
    cudaFuncSetAttribute(gemm_mma<4,0>, cudaFuncAttributeMaxDynamicSharedMemorySize, GEMM_SMEM);

    // --- pack weights ---
    {
        long t = (long)Dz * (Dz >> 3);
        int blks = (int)((t + 255) / 256);
        const int WSZ = Dz * Dz;
        pack_w_kernel<<<blks, 256>>>(W_omega, wcat + 0 * WSZ, Dz, Dz);
        pack_w_kernel<<<blks, 256>>>(W_mag,   wcat + 1 * WSZ, Dz, Dz);
        pack_w_kernel<<<blks, 256>>>(W_gate,  wcat + 2 * WSZ, Dz, Dz);
        pack_w_kernel<<<blks, 256>>>(W_qoff,  wcat + 3 * WSZ, Dz, Dz);
        pack_w_kernel<<<blks, 256>>>(W_p1,    wcat + 4 * WSZ, Dz, Dz);
        pack_w_kernel<<<blks, 256>>>(W_p2,    wp2, Dz, Dz);
        long t1 = (long)D2 * (D4 >> 3);
        pack_w_kernel<<<(int)((t1 + 255) / 256), 256>>>(W_o1, wo1, D4, D2);
        long t2 = (long)Dz * (D2 >> 3);
        pack_w_kernel<<<(int)((t2 + 255) / 256), 256>>>(W_o2, wo2, D2, Dz);
    }

    // --- pack x ---
    {
        long t = (long)Mz * Dz / 8;
        pack_a_kernel<<<(int)((t + 255) / 256), 256>>>(x, xp, Dz, t);
    }

    dim3 blk(256);

    // fused projections (omega, mag, gate, qoff, p1), grid (20, 256)
    proj_gemm<<<dim3(20, Mz / 128), blk, GEMM_SMEM>>>(
        xp, wcat,
        b_omega, b_mag, b_gate, b_qoff, b_p1,
        p_omega, p_mag, p_gate, p_qoff, p1p);

    // p2 -> phii (fp16 row-major)
    gemm_mma<0,2><<<dim3(4, Mz / 128), blk, GEMM_SMEM>>>(
        p1p, wp2, b_p2, nullptr, p_phii, nullptr, Dz, Dz);

    // parallel scan + fused LN/pack
    dim3 sgrid(SCH, Bz);
    scan_sum1<<<sgrid, 256>>>(iscale);
    scan_pfx1<<<NCHAN / 256, 256>>>();
    scan_sum2<<<sgrid, 256>>>(iscale);
    scan_pfx2<<<NCHAN / 256, 256>>>();
    scan_final_ln<<<sgrid, 256>>>(iscale, ln_g, ln_b, cxp);

    // output MLP
    gemm_mma<1,1><<<dim3(D2 / 128, Mz / 128), blk, GEMM_SMEM>>>(
        cxp, wo1, b_o1, nullptr, hp, nullptr, D2, D4);
    gemm_mma<4,0><<<dim3(Dz / 128, Mz / 128), blk, GEMM_SMEM>>>(
        hp, wo2, b_o2, out, nullptr, x, Dz, D2);
}

// round 14
// speedup vs baseline: 1.0196x; 1.0196x over previous
#include <cuda_runtime.h>
#include <cuda_fp16.h>
#include <math.h>
#include <stdint.h>

#define Bz 8
#define Sz 4096
#define Dz 512
#define Mz (Bz * Sz)          // 32768 rows
#define D4 (4 * Dz)           // 2048
#define D2 (2 * Dz)           // 1024

#define SCH 64                // scan chunks
#define SLEN (Sz / SCH)       // 64 steps per chunk
#define NCHAN (Bz * Dz)       // 4096 channels

// ---------------------------------------------------------------------------
// Scratch (static device globals; no allocation)
// ---------------------------------------------------------------------------
// scan inputs, fp16 row-major [Mz, Dz]
__device__ __half g_omega[(size_t)Mz * Dz];
__device__ __half g_mag  [(size_t)Mz * Dz];
__device__ __half g_gate [(size_t)Mz * Dz];
__device__ __half g_qoff [(size_t)Mz * Dz];
__device__ __half g_phii [(size_t)Mz * Dz];

// scan chunk statistics [chunk][channel]
__device__ float g_sphi[SCH * NCHAN];
__device__ float g_sm  [SCH * NCHAN];
__device__ float g_smr [SCH * NCHAN];
__device__ float g_smi [SCH * NCHAN];

// packed fp16 activations (SW128 tile-blocked)
__device__ __half g_xp  [(size_t)Mz * Dz];
__device__ __half g_p1p [(size_t)Mz * Dz];
__device__ __half g_ctxp[(size_t)Mz * D4];
__device__ __half g_hp  [(size_t)Mz * D2];

// fp16 weights (transposed to [N,K], SW128 tile-blocked)
__device__ __half g_wcat[5 * Dz * Dz];          // [omega|mag|gate|qoff|p1]
__device__ __half g_wp2[Dz * Dz];
__device__ __half g_wo1[(size_t)D4 * D2];
__device__ __half g_wo2[D2 * Dz];

// ---------------------------------------------------------------------------
// PTX helpers
// ---------------------------------------------------------------------------
__device__ __forceinline__ uint32_t smem_u32(const void* p) {
    uint32_t a;
    asm("{ .reg .u64 t; cvta.to.shared.u64 t, %1; cvt.u32.u64 %0, t; }" : "=r"(a) : "l"(p));
    return a;
}

__device__ __forceinline__ void cp16(uint32_t dst, const void* src) {
    asm volatile("cp.async.cg.shared.global [%0], [%1], 16;" :: "r"(dst), "l"(src));
}
#define CP_COMMIT() asm volatile("cp.async.commit_group;" ::: "memory")
#define CP_WAIT(n)  asm volatile("cp.async.wait_group %0;" :: "n"(n) : "memory")

__device__ __forceinline__ void ldsm4(uint32_t* r, uint32_t addr) {
    asm volatile("ldmatrix.sync.aligned.m8n8.x4.shared.b16 {%0,%1,%2,%3}, [%4];"
                 : "=r"(r[0]), "=r"(r[1]), "=r"(r[2]), "=r"(r[3]) : "r"(addr));
}

__device__ __forceinline__ void mma16816(float* d, const uint32_t* a, uint32_t b0, uint32_t b1) {
    asm volatile(
        "mma.sync.aligned.m16n8k16.row.col.f32.f16.f16.f32 "
        "{%0,%1,%2,%3}, {%4,%5,%6,%7}, {%8,%9}, {%0,%1,%2,%3};"
        : "+f"(d[0]), "+f"(d[1]), "+f"(d[2]), "+f"(d[3])
        : "r"(a[0]), "r"(a[1]), "r"(a[2]), "r"(a[3]), "r"(b0), "r"(b1));
}

__device__ __forceinline__ uint32_t sw128(uint32_t b) { return b ^ ((b >> 3) & 0x70); }

// read a float2 (2 fp16) from the SW128 tile-blocked layout at (row, d0)
__device__ __forceinline__ float2 ldxp2(const __half* xp, int row, int d0, int nkc) {
    size_t blk = (size_t)(row >> 7) * nkc + (d0 >> 6);
    uint32_t sw = sw128((uint32_t)((row & 127) * 128 + (d0 & 63) * 2));
    return __half22float2(*(const __half2*)((const char*)xp + blk * 16384 + sw));
}

// ---------------------------------------------------------------------------
// Packing kernels
// ---------------------------------------------------------------------------
__global__ void pack_a_kernel(const float* __restrict__ A,
                              __half* __restrict__ P,
                              int K, long total8)
{
    long idx = (long)blockIdx.x * blockDim.x + threadIdx.x;
    if (idx >= total8) return;
    int kk8 = K >> 3;
    int row = (int)(idx / kk8);
    int k   = (int)(idx % kk8) << 3;

    const float4* p = (const float4*)(A + (size_t)row * K + k);
    float4 a = p[0], b = p[1];
    float v[8] = {a.x, a.y, a.z, a.w, b.x, b.y, b.z, b.w};

    __align__(16) __half h[8];
#pragma unroll
    for (int i = 0; i < 8; i++) h[i] = __float2half(v[i]);

    int mt = row >> 7, r = row & 127, ch = k >> 6, c = k & 63;
    size_t blk = (size_t)mt * (K >> 6) + ch;
    uint32_t sw = sw128((uint32_t)(r * 128 + c * 2));
    size_t off = blk * 16384 + sw;
    *(uint4*)((char*)P + off) = *(const uint4*)h;
}

__global__ void pack_w_kernel(const float* __restrict__ W,
                              __half* __restrict__ P,
                              int K, int N)
{
    long idx = (long)blockIdx.x * blockDim.x + threadIdx.x;
    long total = (long)N * (K >> 3);
    if (idx >= total) return;
    int n  = (int)(idx % N);
    int kg = (int)(idx / N);
    int k  = kg << 3;

    __align__(16) __half h[8];
#pragma unroll
    for (int i = 0; i < 8; i++) h[i] = __float2half(W[(size_t)(k + i) * N + n]);

    int nt = n >> 7, rn = n & 127, ch = k >> 6, c = k & 63;
    size_t blk = (size_t)nt * (K >> 6) + ch;
    uint32_t sw = sw128((uint32_t)(rn * 128 + c * 2));
    size_t off = blk * 16384 + sw;
    *(uint4*)((char*)P + off) = *(const uint4*)h;
}

// ---------------------------------------------------------------------------
// MMA core: BM=128, BN=128, BK=64, 256 threads (8 warps: 4 wm x 2 wn),
// warp tile 32x64. Stage = A + B = 32KB. 2-stage pipeline, 2 CTAs/SM. (R12)
// ---------------------------------------------------------------------------
#define TB 16384
#define STAGE_BYTES (2 * TB)
#define GEMM_SMEM   (2 * STAGE_BYTES)   // 64KB -> 2 CTAs/SM

__device__ __forceinline__ void mma_chunk(uint32_t sA, uint32_t sB,
                                          int wm, int wn, int lane,
                                          float acc[2][8][4])
{
    const int a_row = lane & 15;
    const int a_kb  = (lane >> 4) * 16;
#pragma unroll
    for (int k16 = 0; k16 < 4; ++k16) {
        const int kb = k16 * 32 + a_kb;
        uint32_t ah[2][4], bh[4][4];
#pragma unroll
        for (int im = 0; im < 2; im++) {
            uint32_t b = (uint32_t)((wm * 32 + im * 16 + a_row) * 128 + kb);
            ldsm4(ah[im], sA + sw128(b));
        }
#pragma unroll
        for (int j2 = 0; j2 < 4; j2++) {
            uint32_t b = (uint32_t)((wn * 64 + j2 * 16 + a_row) * 128 + kb);
            ldsm4(bh[j2], sB + sw128(b));
        }
#pragma unroll
        for (int im = 0; im < 2; im++)
#pragma unroll
            for (int jn = 0; jn < 8; jn++) {
                const int j2 = jn >> 1, jo = jn & 1;
                mma16816(acc[im][jn], ah[im], bh[j2][jo], bh[j2][2 + jo]);
            }
    }
}

__device__ __forceinline__ float gelu_exact(float v) {
    return 0.5f * v * (1.0f + erff(v * 0.70710678118654752f));
}

__device__ __forceinline__ void copy_stage(uint32_t sdst,
                                           const char* A, const char* B, int tid)
{
#pragma unroll
    for (int j = 0; j < 4; j++) {
        uint32_t o = (uint32_t)tid * 16 + j * 4096;
        cp16(sdst + o,      A + o);
        cp16(sdst + TB + o, B + o);
    }
}

// ---------------------------------------------------------------------------
// Fused projection GEMM: grid (20, 256). group = bx>>2 (0..4), n-tile = bx&3.
// group: 0 omega, 1 mag(sig5), 2 gate(sig), 3 qoff -> fp16 row-major out,
//        4 p1(gelu) -> packed fp16
// ---------------------------------------------------------------------------
__global__ __launch_bounds__(256, 2)
void proj_gemm(const __half* __restrict__ Ap, const __half* __restrict__ W,
               const float* __restrict__ b_om, const float* __restrict__ b_mg,
               const float* __restrict__ b_gt, const float* __restrict__ b_qo,
               const float* __restrict__ b_p1,
               __half* __restrict__ c_om, __half* __restrict__ c_mg,
               __half* __restrict__ c_gt, __half* __restrict__ c_qo,
               __half* __restrict__ p1p)
{
    extern __shared__ __align__(1024) char dsmem[];
    const uint32_t sbase = smem_u32(dsmem);

    const int tid  = threadIdx.x;
    const int wid  = tid >> 5;
    const int lane = tid & 31;
    const int wm   = wid >> 1;      // 0..3 (32 rows each)
    const int wn   = wid & 1;       // 0..1 (64 cols each)

    const int group = blockIdx.x >> 2;
    const int ntile = blockIdx.x & 3;

    const int nch = 8;  // K=512
    const char* srcA = (const char*)Ap + (size_t)blockIdx.y * nch * TB;
    const char* srcB = (const char*)W + ((size_t)group * 4 + ntile) * nch * TB;

    float acc[2][8][4];
#pragma unroll
    for (int i = 0; i < 2; i++)
#pragma unroll
        for (int j = 0; j < 8; j++)
#pragma unroll
            for (int q = 0; q < 4; q++) acc[i][j][q] = 0.f;

    copy_stage(sbase, srcA, srcB, tid);
    CP_COMMIT();

    for (int ch = 0; ch < nch; ++ch) {
        if (ch + 1 < nch) {
            copy_stage(sbase + ((ch + 1) & 1) * STAGE_BYTES,
                       srcA + (size_t)(ch + 1) * TB, srcB + (size_t)(ch + 1) * TB, tid);
            CP_COMMIT();
            CP_WAIT(1);
        } else {
            CP_WAIT(0);
        }
        __syncthreads();

        const uint32_t sA = sbase + (ch & 1) * STAGE_BYTES;
        mma_chunk(sA, sA + TB, wm, wn, lane, acc);
        __syncthreads();
    }

    // ---------------- epilogue ----------------
    const float* bias = (group == 0) ? b_om : (group == 1) ? b_mg :
                        (group == 2) ? b_gt : (group == 3) ? b_qo : b_p1;
    __half* cout = (group == 0) ? c_om : (group == 1) ? c_mg :
                   (group == 2) ? c_gt : c_qo;

    const int m0  = blockIdx.y * 128 + wm * 32 + (lane >> 2);
    const int nl0 = ntile * 128 + wn * 64 + (lane & 3) * 2;

#pragma unroll
    for (int im = 0; im < 2; im++) {
#pragma unroll
        for (int half = 0; half < 2; half++) {
            const int row = m0 + im * 16 + half * 8;
#pragma unroll
            for (int jn = 0; jn < 8; jn++) {
                const int col = nl0 + jn * 8;   // 0..511 within group
                float v0 = acc[im][jn][half * 2 + 0] + bias[col];
                float v1 = acc[im][jn][half * 2 + 1] + bias[col + 1];
                if (group == 1) { v0 = 5.f / (1.f + expf(-v0)); v1 = 5.f / (1.f + expf(-v1)); }
                else if (group == 2) { v0 = 1.f / (1.f + expf(-v0)); v1 = 1.f / (1.f + expf(-v1)); }
                else if (group == 4) { v0 = gelu_exact(v0); v1 = gelu_exact(v1); }

                __half h0 = __float2half(v0);
                __half h1 = __float2half(v1);
                uint32_t hp = ((uint32_t)__half_as_ushort(h1) << 16) | __half_as_ushort(h0);
                if (group == 4) {
                    size_t blk = (size_t)(row >> 7) * 8 + (col >> 6);
                    uint32_t sw = sw128((uint32_t)((row & 127) * 128 + (col & 63) * 2));
                    size_t off = blk * 16384 + sw;
                    *(uint32_t*)((char*)p1p + off) = hp;
                } else {
                    *(uint32_t*)(cout + (size_t)row * Dz + col) = hp;
                }
            }
        }
    }
}

// ---------------------------------------------------------------------------
// generic GEMM: EPI 0 none, 1 gelu, 4 +resid.
// OUT: 0 = fp32 C, 1 = packed fp16 (SW128 blocked), 2 = fp16 row-major
// grid (N/128, M/128)
// ---------------------------------------------------------------------------
template <int EPI, int OUT>
__global__ __launch_bounds__(256, 2)
void gemm_mma(const __half* __restrict__ Ap, const __half* __restrict__ Bp,
              const float* __restrict__ bias, float* __restrict__ C,
              __half* __restrict__ Hout,
              const float* __restrict__ resid, int N, int K)
{
    extern __shared__ __align__(1024) char dsmem[];
    const uint32_t sbase = smem_u32(dsmem);

    const int tid  = threadIdx.x;
    const int wid  = tid >> 5;
    const int lane = tid & 31;
    const int wm   = wid >> 1;
    const int wn   = wid & 1;

    const int nch = K >> 6;
    const char* srcA = (const char*)Ap + (size_t)blockIdx.y * nch * TB;
    const char* srcB = (const char*)Bp + (size_t)blockIdx.x * nch * TB;

    float acc[2][8][4];
#pragma unroll
    for (int i = 0; i < 2; i++)
#pragma unroll
        for (int j = 0; j < 8; j++)
#pragma unroll
            for (int q = 0; q < 4; q++) acc[i][j][q] = 0.f;

    copy_stage(sbase, srcA, srcB, tid);
    CP_COMMIT();

    for (int ch = 0; ch < nch; ++ch) {
        if (ch + 1 < nch) {
            copy_stage(sbase + ((ch + 1) & 1) * STAGE_BYTES,
                       srcA + (size_t)(ch + 1) * TB, srcB + (size_t)(ch + 1) * TB, tid);
            CP_COMMIT();
            CP_WAIT(1);
        } else {
            CP_WAIT(0);
        }
        __syncthreads();

        const uint32_t sA = sbase + (ch & 1) * STAGE_BYTES;
        mma_chunk(sA, sA + TB, wm, wn, lane, acc);
        __syncthreads();
    }

    const int m0 = blockIdx.y * 128 + wm * 32 + (lane >> 2);
    const int n0 = blockIdx.x * 128 + wn * 64 + (lane & 3) * 2;
    const int nkc = N >> 6;

#pragma unroll
    for (int im = 0; im < 2; im++) {
#pragma unroll
        for (int half = 0; half < 2; half++) {
            const int row = m0 + im * 16 + half * 8;
            float* crow = (OUT == 0) ? (C + (size_t)row * N) : nullptr;
            const float* rrow = (EPI == 4) ? (resid + (size_t)row * N) : nullptr;
#pragma unroll
            for (int jn = 0; jn < 8; jn++) {
                const int col = n0 + jn * 8;
                float v0 = acc[im][jn][half * 2 + 0] + bias[col];
                float v1 = acc[im][jn][half * 2 + 1] + bias[col + 1];
                if (EPI == 1) { v0 = gelu_exact(v0); v1 = gelu_exact(v1); }
                else if (EPI == 4) { v0 += rrow[col]; v1 += rrow[col + 1]; }

                if (OUT == 0) {
                    *(float2*)(crow + col) = make_float2(v0, v1);
                } else {
                    __half h0 = __float2half(v0);
                    __half h1 = __float2half(v1);
                    uint32_t hp = ((uint32_t)__half_as_ushort(h1) << 16) | __half_as_ushort(h0);
                    if (OUT == 1) {
                        size_t blk = (size_t)(row >> 7) * nkc + (col >> 6);
                        uint32_t sw = sw128((uint32_t)((row & 127) * 128 + (col & 63) * 2));
                        size_t off = blk * 16384 + sw;
                        *(uint32_t*)((char*)Hout + off) = hp;
                    } else {
                        *(uint32_t*)(Hout + (size_t)row * N + col) = hp;
                    }
                }
            }
        }
    }
}

// ---------------------------------------------------------------------------
// Parallel scan (fp16 inputs incl. packed x, fp32 accumulation)
// ---------------------------------------------------------------------------
__device__ __forceinline__ float2 ldh2(const __half* p) {
    return __half22float2(*(const __half2*)p);
}

__global__ __launch_bounds__(256)
void scan_sum1(const float* __restrict__ iscale)
{
    const int chunk = blockIdx.x, b = blockIdx.y;
    const int d0 = threadIdx.x * 2;
    float2 is2 = *(const float2*)(iscale + d0);
    const float i0 = fabsf(is2.x), i1 = fabsf(is2.y);

    size_t idx = ((size_t)b * Sz + (size_t)chunk * SLEN) * Dz + d0;
    float sp0 = 0.f, sp1 = 0.f, sm0 = 0.f, sm1 = 0.f;
#pragma unroll 4
    for (int s = 0; s < SLEN; ++s) {
        float2 g = ldh2(g_gate + idx);
        float2 o = ldh2(g_omega + idx);
        float2 m = ldh2(g_mag + idx);
        sp0 += g.x * o.x * i0;  sp1 += g.y * o.y * i1;
        sm0 += m.x;             sm1 += m.y;
        idx += Dz;
    }
    int ch = b * Dz + d0;
    *(float2*)&g_sphi[chunk * NCHAN + ch] = make_float2(sp0, sp1);
    *(float2*)&g_sm  [chunk * NCHAN + ch] = make_float2(sm0, sm1);
}

__global__ void scan_pfx1()
{
    int ch = blockIdx.x * blockDim.x + threadIdx.x;
    if (ch >= NCHAN) return;
    float rp = 0.f, rm = 0.f;
    for (int c = 0; c < SCH; ++c) {
        int i = c * NCHAN + ch;
        float tp = g_sphi[i]; g_sphi[i] = rp; rp += tp;
        float tm = g_sm[i];   g_sm[i]   = rm; rm += tm;
    }
}

__global__ __launch_bounds__(256)
void scan_sum2(const float* __restrict__ iscale)
{
    const int chunk = blockIdx.x, b = blockIdx.y;
    const int d0 = threadIdx.x * 2;
    float2 is2 = *(const float2*)(iscale + d0);
    const float i0 = fabsf(is2.x), i1 = fabsf(is2.y);
    const int ch = b * Dz + d0;
    float2 phib = *(const float2*)&g_sphi[chunk * NCHAN + ch];

    int row = b * Sz + chunk * SLEN;
    size_t idx = (size_t)row * Dz + d0;
    float pc0 = 0.f, pc1 = 0.f, r0 = 0.f, r1 = 0.f, q0 = 0.f, q1 = 0.f;
#pragma unroll 4
    for (int s = 0; s < SLEN; ++s) {
        float2 g = ldh2(g_gate + idx);
        float2 o = ldh2(g_omega + idx);
        float2 m = ldh2(g_mag + idx);
        float2 xv = ldxp2(g_xp, row + s, d0, 8);
        float2 pv = ldh2(g_phii + idx);
        pc0 += g.x * o.x * i0;
        pc1 += g.y * o.y * i1;
        float c, sn;
        __sincosf(pv.x + phib.x + pc0, &sn, &c);
        float wc = m.x * xv.x;
        r0 += wc * c;  q0 += wc * sn;
        __sincosf(pv.y + phib.y + pc1, &sn, &c);
        wc = m.y * xv.y;
        r1 += wc * c;  q1 += wc * sn;
        idx += Dz;
    }
    *(float2*)&g_smr[chunk * NCHAN + ch] = make_float2(r0, r1);
    *(float2*)&g_smi[chunk * NCHAN + ch] = make_float2(q0, q1);
}

__global__ void scan_pfx2()
{
    int ch = blockIdx.x * blockDim.x + threadIdx.x;
    if (ch >= NCHAN) return;
    float rr = 0.f, ri = 0.f;
    for (int c = 0; c < SCH; ++c) {
        int i = c * NCHAN + ch;
        float tr = g_smr[i]; g_smr[i] = rr; rr += tr;
        float ti = g_smi[i]; g_smi[i] = ri; ri += ti;
    }
}

__device__ __forceinline__ float block_reduce_sum(float val)
{
    __shared__ float sh[8];
    int lane = threadIdx.x & 31, w = threadIdx.x >> 5;
    __syncthreads();
#pragma unroll
    for (int o = 16; o > 0; o >>= 1) val += __shfl_down_sync(0xffffffffu, val, o);
    if (lane == 0) sh[w] = val;
    __syncthreads();
    if (w == 0) {
        val = (lane < 8) ? sh[lane] : 0.f;
#pragma unroll
        for (int o = 4; o > 0; o >>= 1) val += __shfl_down_sync(0xffffffffu, val, o);
        if (lane == 0) sh[0] = val;
    }
    __syncthreads();
    return sh[0];
}

__global__ __launch_bounds__(256)
void scan_final_ln(const float* __restrict__ iscale,
                   const float* __restrict__ gamma, const float* __restrict__ beta,
                   __half* __restrict__ Pctx)
{
    const int chunk = blockIdx.x, b = blockIdx.y;
    const int d0 = threadIdx.x * 2;
    float2 is2 = *(const float2*)(iscale + d0);
    const float i0 = fabsf(is2.x), i1 = fabsf(is2.y);
    const int ch = b * Dz + d0;

    float2 phib = *(const float2*)&g_sphi[chunk * NCHAN + ch];
    float2 mr   = *(const float2*)&g_smr [chunk * NCHAN + ch];
    float2 mi   = *(const float2*)&g_smi [chunk * NCHAN + ch];
    float2 cm   = *(const float2*)&g_sm  [chunk * NCHAN + ch];

    float2 gg[4], bb[4];
#pragma unroll
    for (int j = 0; j < 4; j++) {
        gg[j] = *(const float2*)(gamma + j * Dz + d0);
        bb[j] = *(const float2*)(beta  + j * Dz + d0);
    }

    int row = b * Sz + chunk * SLEN;
    size_t idx = (size_t)row * Dz + d0;
    float pc0 = 0.f, pc1 = 0.f;

    for (int s = 0; s < SLEN; ++s, ++row, idx += Dz) {
        float2 g  = ldh2(g_gate + idx);
        float2 o  = ldh2(g_omega + idx);
        float2 m  = ldh2(g_mag + idx);
        float2 xv = ldxp2(g_xp, row, d0, 8);
        float2 pv = ldh2(g_phii + idx);
        float2 qv = ldh2(g_qoff + idx);

        float v[2][4];
        {
            pc0 += g.x * o.x * i0;
            float phi = pv.x + phib.x + pc0;
            float c, sn; __sincosf(phi, &sn, &c);
            float wc = m.x * xv.x;
            mr.x += wc * c;  mi.x += wc * sn;  cm.x += m.x;
            float r = rsqrtf(cm.x + 1e-8f);
            float mrn = mr.x * r, min_ = mi.x * r;
            float cq, sq; __sincosf(phi + qv.x, &sq, &cq);
            v[0][0] = xv.x * c;  v[0][1] = xv.x * sn;
            v[0][2] = mrn * cq + min_ * sq;  v[0][3] = min_ * cq - mrn * sq;
        }
        {
            pc1 += g.y * o.y * i1;
            float phi = pv.y + phib.y + pc1;
            float c, sn; __sincosf(phi, &sn, &c);
            float wc = m.y * xv.y;
            mr.y += wc * c;  mi.y += wc * sn;  cm.y += m.y;
            float r = rsqrtf(cm.y + 1e-8f);
            float mrn = mr.y * r, min_ = mi.y * r;
            float cq, sq; __sincosf(phi + qv.y, &sq, &cq);
            v[1][0] = xv.y * c;  v[1][1] = xv.y * sn;
            v[1][2] = mrn * cq + min_ * sq;  v[1][3] = min_ * cq - mrn * sq;
        }

        float part = 0.f;
#pragma unroll
        for (int j = 0; j < 4; j++) part += v[0][j] + v[1][j];
        float mean = block_reduce_sum(part) * (1.0f / (float)D4);

        float sqp = 0.f;
#pragma unroll
        for (int j = 0; j < 4; j++) {
            float a0 = v[0][j] - mean, a1 = v[1][j] - mean;
            sqp += a0 * a0 + a1 * a1;
        }
        float rstd = rsqrtf(block_reduce_sum(sqp) * (1.0f / (float)D4) + 1e-5f);

        const size_t blkrow = (size_t)(row >> 7) * (D4 >> 6);
        const uint32_t rsw = (uint32_t)((row & 127) * 128);
#pragma unroll
        for (int j = 0; j < 4; j++) {
            float y0 = (v[0][j] - mean) * rstd * gg[j].x + bb[j].x;
            float y1 = (v[1][j] - mean) * rstd * gg[j].y + bb[j].y;
            __half h0 = __float2half(y0);
            __half h1 = __float2half(y1);
            uint32_t hp = ((uint32_t)__half_as_ushort(h1) << 16) | __half_as_ushort(h0);
            const int col = j * Dz + d0;
            size_t blk = blkrow + (col >> 6);
            uint32_t sw = sw128(rsw + (uint32_t)((col & 63) * 2));
            size_t off = blk * 16384 + sw;
            *(uint32_t*)((char*)Pctx + off) = hp;
        }
    }
}

// ---------------------------------------------------------------------------
// launch
// ---------------------------------------------------------------------------
static inline void* sym(const void* s) { void* p = nullptr; cudaGetSymbolAddress(&p, s); return p; }

extern "C" void kernel_launch(void* const* d_in, const int* in_sizes, int n_in,
                              void* d_out, int out_size)
{
    const float* x       = (const float*)d_in[0];
    const float* W_omega = (const float*)d_in[1];
    const float* b_omega = (const float*)d_in[2];
    const float* W_p1    = (const float*)d_in[3];
    const float* b_p1    = (const float*)d_in[4];
    const float* W_p2    = (const float*)d_in[5];
    const float* b_p2    = (const float*)d_in[6];
    const float* W_gate  = (const float*)d_in[7];
    const float* b_gate  = (const float*)d_in[8];
    const float* iscale  = (const float*)d_in[9];
    const float* W_mag   = (const float*)d_in[10];
    const float* b_mag   = (const float*)d_in[11];
    const float* W_qoff  = (const float*)d_in[12];
    const float* b_qoff  = (const float*)d_in[13];
    const float* ln_g    = (const float*)d_in[14];
    const float* ln_b    = (const float*)d_in[15];
    const float* W_o1    = (const float*)d_in[16];
    const float* b_o1    = (const float*)d_in[17];
    const float* W_o2    = (const float*)d_in[18];
    const float* b_o2    = (const float*)d_in[19];
    float* out = (float*)d_out;

    __half* p_omega = (__half*)sym(g_omega);
    __half* p_mag   = (__half*)sym(g_mag);
    __half* p_gate  = (__half*)sym(g_gate);
    __half* p_qoff  = (__half*)sym(g_qoff);
    __half* p_phii  = (__half*)sym(g_phii);

    __half* xp   = (__half*)sym(g_xp);
    __half* p1p  = (__half*)sym(g_p1p);
    __half* cxp  = (__half*)sym(g_ctxp);
    __half* hp   = (__half*)sym(g_hp);

    __half* wcat = (__half*)sym(g_wcat);
    __half* wp2  = (__half*)sym(g_wp2);
    __half* wo1  = (__half*)sym(g_wo1);
    __half* wo2  = (__half*)sym(g_wo2);

    cudaFuncSetAttribute(proj_gemm,     cudaFuncAttributeMaxDynamicSharedMemorySize, GEMM_SMEM);
    cudaFuncSetAttribute(gemm_mma<0,2>, cudaFuncAttributeMaxDynamicSharedMemorySize, GEMM_SMEM);
    cudaFuncSetAttribute(gemm_mma<1,1>, cudaFuncAttributeMaxDynamicSharedMemorySize, GEMM_SMEM);
    cudaFuncSetAttribute(gemm_mma<4,0>, cudaFuncAttributeMaxDynamicSharedMemorySize, GEMM_SMEM);

    // --- pack weights ---
    {
        long t = (long)Dz * (Dz >> 3);
        int blks = (int)((t + 255) / 256);
        const int WSZ = Dz * Dz;
        pack_w_kernel<<<blks, 256>>>(W_omega, wcat + 0 * WSZ, Dz, Dz);
        pack_w_kernel<<<blks, 256>>>(W_mag,   wcat + 1 * WSZ, Dz, Dz);
        pack_w_kernel<<<blks, 256>>>(W_gate,  wcat + 2 * WSZ, Dz, Dz);
        pack_w_kernel<<<blks, 256>>>(W_qoff,  wcat + 3 * WSZ, Dz, Dz);
        pack_w_kernel<<<blks, 256>>>(W_p1,    wcat + 4 * WSZ, Dz, Dz);
        pack_w_kernel<<<blks, 256>>>(W_p2,    wp2, Dz, Dz);
        long t1 = (long)D2 * (D4 >> 3);
        pack_w_kernel<<<(int)((t1 + 255) / 256), 256>>>(W_o1, wo1, D4, D2);
        long t2 = (long)Dz * (D2 >> 3);
        pack_w_kernel<<<(int)((t2 + 255) / 256), 256>>>(W_o2, wo2, D2, Dz);
    }

    // --- pack x ---
    {
        long t = (long)Mz * Dz / 8;
        pack_a_kernel<<<(int)((t + 255) / 256), 256>>>(x, xp, Dz, t);
    }

    dim3 blk(256);

    // fused projections (omega, mag, gate, qoff, p1), grid (20, 256)
    proj_gemm<<<dim3(20, Mz / 128), blk, GEMM_SMEM>>>(
        xp, wcat,
        b_omega, b_mag, b_gate, b_qoff, b_p1,
        p_omega, p_mag, p_gate, p_qoff, p1p);

    // p2 -> phii (fp16 row-major)
    gemm_mma<0,2><<<dim3(4, Mz / 128), blk, GEMM_SMEM>>>(
        p1p, wp2, b_p2, nullptr, p_phii, nullptr, Dz, Dz);

    // parallel scan + fused LN/pack
    dim3 sgrid(SCH, Bz);
    scan_sum1<<<sgrid, 256>>>(iscale);
    scan_pfx1<<<NCHAN / 256, 256>>>();
    scan_sum2<<<sgrid, 256>>>(iscale);
    scan_pfx2<<<NCHAN / 256, 256>>>();
    scan_final_ln<<<sgrid, 256>>>(iscale, ln_g, ln_b, cxp);

    // output MLP
    gemm_mma<1,1><<<dim3(D2 / 128, Mz / 128), blk, GEMM_SMEM>>>(
        cxp, wo1, b_o1, nullptr, hp, nullptr, D2, D4);
    gemm_mma<4,0><<<dim3(Dz / 128, Mz / 128), blk, GEMM_SMEM>>>(
        hp, wo2, b_o2, out, nullptr, x, Dz, D2);
}

// round 15
// speedup vs baseline: 1.0289x; 1.0091x over previous
#include <cuda_runtime.h>
#include <cuda_fp16.h>
#include <math.h>
#include <stdint.h>

#define Bz 8
#define Sz 4096
#define Dz 512
#define Mz (Bz * Sz)          // 32768 rows
#define D4 (4 * Dz)           // 2048
#define D2 (2 * Dz)           // 1024

#define SCH 64                // scan chunks
#define SLEN (Sz / SCH)       // 64 steps per chunk
#define NCHAN (Bz * Dz)       // 4096 channels

// ---------------------------------------------------------------------------
// Scratch (static device globals; no allocation)
// ---------------------------------------------------------------------------
// scan inputs, fp16 row-major [Mz, Dz]
__device__ __half g_omega[(size_t)Mz * Dz];
__device__ __half g_mag  [(size_t)Mz * Dz];
__device__ __half g_gate [(size_t)Mz * Dz];
__device__ __half g_phii [(size_t)Mz * Dz];
// packed (cos(qoff) lo, sin(qoff) hi) per element, row-major
__device__ uint32_t g_qsc [(size_t)Mz * Dz];

// scan chunk statistics [chunk][channel]
__device__ float g_sphi[SCH * NCHAN];
__device__ float g_sm  [SCH * NCHAN];
__device__ float g_smr [SCH * NCHAN];
__device__ float g_smi [SCH * NCHAN];

// packed fp16 activations (SW128 tile-blocked)
__device__ __half g_xp  [(size_t)Mz * Dz];
__device__ __half g_p1p [(size_t)Mz * Dz];
__device__ __half g_ctxp[(size_t)Mz * D4];
__device__ __half g_hp  [(size_t)Mz * D2];

// fp16 weights (transposed to [N,K], SW128 tile-blocked)
__device__ __half g_wcat[5 * Dz * Dz];          // [omega|mag|gate|qoff|p1]
__device__ __half g_wp2[Dz * Dz];
__device__ __half g_wo1[(size_t)D4 * D2];
__device__ __half g_wo2[D2 * Dz];

// ---------------------------------------------------------------------------
// PTX helpers
// ---------------------------------------------------------------------------
__device__ __forceinline__ uint32_t smem_u32(const void* p) {
    uint32_t a;
    asm("{ .reg .u64 t; cvta.to.shared.u64 t, %1; cvt.u32.u64 %0, t; }" : "=r"(a) : "l"(p));
    return a;
}

__device__ __forceinline__ void cp16(uint32_t dst, const void* src) {
    asm volatile("cp.async.cg.shared.global [%0], [%1], 16;" :: "r"(dst), "l"(src));
}
#define CP_COMMIT() asm volatile("cp.async.commit_group;" ::: "memory")
#define CP_WAIT(n)  asm volatile("cp.async.wait_group %0;" :: "n"(n) : "memory")

__device__ __forceinline__ void ldsm4(uint32_t* r, uint32_t addr) {
    asm volatile("ldmatrix.sync.aligned.m8n8.x4.shared.b16 {%0,%1,%2,%3}, [%4];"
                 : "=r"(r[0]), "=r"(r[1]), "=r"(r[2]), "=r"(r[3]) : "r"(addr));
}

__device__ __forceinline__ void mma16816(float* d, const uint32_t* a, uint32_t b0, uint32_t b1) {
    asm volatile(
        "mma.sync.aligned.m16n8k16.row.col.f32.f16.f16.f32 "
        "{%0,%1,%2,%3}, {%4,%5,%6,%7}, {%8,%9}, {%0,%1,%2,%3};"
        : "+f"(d[0]), "+f"(d[1]), "+f"(d[2]), "+f"(d[3])
        : "r"(a[0]), "r"(a[1]), "r"(a[2]), "r"(a[3]), "r"(b0), "r"(b1));
}

__device__ __forceinline__ uint32_t sw128(uint32_t b) { return b ^ ((b >> 3) & 0x70); }

// ---------------------------------------------------------------------------
// Fused packing: one launch covers all weights + x.
// blocks [0,768):   6 weights (K=512,N=512), 128 blocks each
// blocks [768,1792): wo1 (K=2048,N=1024)
// blocks [1792,2048): wo2 (K=1024,N=512)
// blocks [2048,10240): pack x (K=512, Mz rows)
// ---------------------------------------------------------------------------
__device__ __forceinline__ void pack_w_do(const float* __restrict__ W,
                                          __half* __restrict__ P,
                                          int K, int N, long idx)
{
    int n  = (int)(idx % N);
    int k  = (int)(idx / N) << 3;
    __align__(16) __half h[8];
#pragma unroll
    for (int i = 0; i < 8; i++) h[i] = __float2half(W[(size_t)(k + i) * N + n]);
    int nt = n >> 7, rn = n & 127, ch = k >> 6, c = k & 63;
    size_t blk = (size_t)nt * (K >> 6) + ch;
    uint32_t sw = sw128((uint32_t)(rn * 128 + c * 2));
    *(uint4*)((char*)P + blk * 16384 + sw) = *(const uint4*)h;
}

__device__ __forceinline__ void pack_a_do(const float* __restrict__ A,
                                          __half* __restrict__ P,
                                          int K, long idx)
{
    int kk8 = K >> 3;
    int row = (int)(idx / kk8);
    int k   = (int)(idx % kk8) << 3;
    const float4* p = (const float4*)(A + (size_t)row * K + k);
    float4 a = p[0], b = p[1];
    float v[8] = {a.x, a.y, a.z, a.w, b.x, b.y, b.z, b.w};
    __align__(16) __half h[8];
#pragma unroll
    for (int i = 0; i < 8; i++) h[i] = __float2half(v[i]);
    int mt = row >> 7, r = row & 127, ch = k >> 6, c = k & 63;
    size_t blk = (size_t)mt * (K >> 6) + ch;
    uint32_t sw = sw128((uint32_t)(r * 128 + c * 2));
    *(uint4*)((char*)P + blk * 16384 + sw) = *(const uint4*)h;
}

__global__ __launch_bounds__(256)
void pack_all(const float* __restrict__ x, __half* __restrict__ xp,
              const float* __restrict__ w0, const float* __restrict__ w1,
              const float* __restrict__ w2, const float* __restrict__ w3,
              const float* __restrict__ w4, const float* __restrict__ w5,
              const float* __restrict__ wo1s, const float* __restrict__ wo2s,
              __half* __restrict__ wcat, __half* __restrict__ wp2d,
              __half* __restrict__ wo1d, __half* __restrict__ wo2d)
{
    const int bid = blockIdx.x;
    if (bid < 768) {
        const int job = bid >> 7;                 // 0..5
        long idx = (long)(bid & 127) * 256 + threadIdx.x;
        const float* src = (job == 0) ? w0 : (job == 1) ? w1 : (job == 2) ? w2 :
                           (job == 3) ? w3 : (job == 4) ? w4 : w5;
        __half* dst = (job < 5) ? (wcat + (size_t)job * Dz * Dz) : wp2d;
        pack_w_do(src, dst, Dz, Dz, idx);
    } else if (bid < 1792) {
        long idx = (long)(bid - 768) * 256 + threadIdx.x;
        pack_w_do(wo1s, wo1d, D4, D2, idx);
    } else if (bid < 2048) {
        long idx = (long)(bid - 1792) * 256 + threadIdx.x;
        pack_w_do(wo2s, wo2d, D2, Dz, idx);
    } else {
        long idx = (long)(bid - 2048) * 256 + threadIdx.x;
        pack_a_do(x, xp, Dz, idx);
    }
}

// ---------------------------------------------------------------------------
// MMA core: BM=128, BN=128, BK=64, 256 threads (8 warps: 4 wm x 2 wn),
// warp tile 32x64. Stage = A + B = 32KB. 2-stage pipeline, 2 CTAs/SM. (R12)
// ---------------------------------------------------------------------------
#define TB 16384
#define STAGE_BYTES (2 * TB)
#define GEMM_SMEM   (2 * STAGE_BYTES)   // 64KB -> 2 CTAs/SM

__device__ __forceinline__ void mma_chunk(uint32_t sA, uint32_t sB,
                                          int wm, int wn, int lane,
                                          float acc[2][8][4])
{
    const int a_row = lane & 15;
    const int a_kb  = (lane >> 4) * 16;
#pragma unroll
    for (int k16 = 0; k16 < 4; ++k16) {
        const int kb = k16 * 32 + a_kb;
        uint32_t ah[2][4], bh[4][4];
#pragma unroll
        for (int im = 0; im < 2; im++) {
            uint32_t b = (uint32_t)((wm * 32 + im * 16 + a_row) * 128 + kb);
            ldsm4(ah[im], sA + sw128(b));
        }
#pragma unroll
        for (int j2 = 0; j2 < 4; j2++) {
            uint32_t b = (uint32_t)((wn * 64 + j2 * 16 + a_row) * 128 + kb);
            ldsm4(bh[j2], sB + sw128(b));
        }
#pragma unroll
        for (int im = 0; im < 2; im++)
#pragma unroll
            for (int jn = 0; jn < 8; jn++) {
                const int j2 = jn >> 1, jo = jn & 1;
                mma16816(acc[im][jn], ah[im], bh[j2][jo], bh[j2][2 + jo]);
            }
    }
}

__device__ __forceinline__ float gelu_exact(float v) {
    return 0.5f * v * (1.0f + erff(v * 0.70710678118654752f));
}

__device__ __forceinline__ void copy_stage(uint32_t sdst,
                                           const char* A, const char* B, int tid)
{
#pragma unroll
    for (int j = 0; j < 4; j++) {
        uint32_t o = (uint32_t)tid * 16 + j * 4096;
        cp16(sdst + o,      A + o);
        cp16(sdst + TB + o, B + o);
    }
}

// ---------------------------------------------------------------------------
// Fused projection GEMM: grid (20, 256). group = bx>>2 (0..4), n-tile = bx&3.
// group: 0 omega, 1 mag(sig5), 2 gate(sig) -> fp16 row-major out,
//        3 qoff -> packed (cos,sin) fp16x2, 4 p1(gelu) -> packed fp16
// ---------------------------------------------------------------------------
__global__ __launch_bounds__(256, 2)
void proj_gemm(const __half* __restrict__ Ap, const __half* __restrict__ W,
               const float* __restrict__ b_om, const float* __restrict__ b_mg,
               const float* __restrict__ b_gt, const float* __restrict__ b_qo,
               const float* __restrict__ b_p1,
               __half* __restrict__ c_om, __half* __restrict__ c_mg,
               __half* __restrict__ c_gt, uint32_t* __restrict__ qsc,
               __half* __restrict__ p1p)
{
    extern __shared__ __align__(1024) char dsmem[];
    const uint32_t sbase = smem_u32(dsmem);

    const int tid  = threadIdx.x;
    const int wid  = tid >> 5;
    const int lane = tid & 31;
    const int wm   = wid >> 1;      // 0..3 (32 rows each)
    const int wn   = wid & 1;       // 0..1 (64 cols each)

    const int group = blockIdx.x >> 2;
    const int ntile = blockIdx.x & 3;

    const int nch = 8;  // K=512
    const char* srcA = (const char*)Ap + (size_t)blockIdx.y * nch * TB;
    const char* srcB = (const char*)W + ((size_t)group * 4 + ntile) * nch * TB;

    float acc[2][8][4];
#pragma unroll
    for (int i = 0; i < 2; i++)
#pragma unroll
        for (int j = 0; j < 8; j++)
#pragma unroll
            for (int q = 0; q < 4; q++) acc[i][j][q] = 0.f;

    copy_stage(sbase, srcA, srcB, tid);
    CP_COMMIT();

    for (int ch = 0; ch < nch; ++ch) {
        if (ch + 1 < nch) {
            copy_stage(sbase + ((ch + 1) & 1) * STAGE_BYTES,
                       srcA + (size_t)(ch + 1) * TB, srcB + (size_t)(ch + 1) * TB, tid);
            CP_COMMIT();
            CP_WAIT(1);
        } else {
            CP_WAIT(0);
        }
        __syncthreads();

        const uint32_t sA = sbase + (ch & 1) * STAGE_BYTES;
        mma_chunk(sA, sA + TB, wm, wn, lane, acc);
        __syncthreads();
    }

    // ---------------- epilogue ----------------
    const float* bias = (group == 0) ? b_om : (group == 1) ? b_mg :
                        (group == 2) ? b_gt : (group == 3) ? b_qo : b_p1;
    __half* cout = (group == 0) ? c_om : (group == 1) ? c_mg : c_gt;

    const int m0  = blockIdx.y * 128 + wm * 32 + (lane >> 2);
    const int nl0 = ntile * 128 + wn * 64 + (lane & 3) * 2;

#pragma unroll
    for (int im = 0; im < 2; im++) {
#pragma unroll
        for (int half = 0; half < 2; half++) {
            const int row = m0 + im * 16 + half * 8;
#pragma unroll
            for (int jn = 0; jn < 8; jn++) {
                const int col = nl0 + jn * 8;   // 0..511 within group
                float v0 = acc[im][jn][half * 2 + 0] + bias[col];
                float v1 = acc[im][jn][half * 2 + 1] + bias[col + 1];

                if (group == 3) {
                    // store (cos, sin) of qoff, packed fp16x2 per element
                    float cq0, sq0, cq1, sq1;
                    __sincosf(v0, &sq0, &cq0);
                    __sincosf(v1, &sq1, &cq1);
                    uint32_t p0 = ((uint32_t)__half_as_ushort(__float2half(sq0)) << 16)
                                | __half_as_ushort(__float2half(cq0));
                    uint32_t p1 = ((uint32_t)__half_as_ushort(__float2half(sq1)) << 16)
                                | __half_as_ushort(__float2half(cq1));
                    *(uint2*)(qsc + (size_t)row * Dz + col) = make_uint2(p0, p1);
                } else if (group == 4) {
                    v0 = gelu_exact(v0); v1 = gelu_exact(v1);
                    __half h0 = __float2half(v0);
                    __half h1 = __float2half(v1);
                    uint32_t hp = ((uint32_t)__half_as_ushort(h1) << 16) | __half_as_ushort(h0);
                    size_t blk = (size_t)(row >> 7) * 8 + (col >> 6);
                    uint32_t sw = sw128((uint32_t)((row & 127) * 128 + (col & 63) * 2));
                    *(uint32_t*)((char*)p1p + blk * 16384 + sw) = hp;
                } else {
                    if (group == 1) { v0 = 5.f / (1.f + expf(-v0)); v1 = 5.f / (1.f + expf(-v1)); }
                    else if (group == 2) { v0 = 1.f / (1.f + expf(-v0)); v1 = 1.f / (1.f + expf(-v1)); }
                    __half h0 = __float2half(v0);
                    __half h1 = __float2half(v1);
                    uint32_t hp = ((uint32_t)__half_as_ushort(h1) << 16) | __half_as_ushort(h0);
                    *(uint32_t*)(cout + (size_t)row * Dz + col) = hp;
                }
            }
        }
    }
}

// ---------------------------------------------------------------------------
// generic GEMM: EPI 0 none, 1 gelu, 4 +resid.
// OUT: 0 = fp32 C, 1 = packed fp16 (SW128 blocked), 2 = fp16 row-major
// grid (N/128, M/128)
// ---------------------------------------------------------------------------
template <int EPI, int OUT>
__global__ __launch_bounds__(256, 2)
void gemm_mma(const __half* __restrict__ Ap, const __half* __restrict__ Bp,
              const float* __restrict__ bias, float* __restrict__ C,
              __half* __restrict__ Hout,
              const float* __restrict__ resid, int N, int K)
{
    extern __shared__ __align__(1024) char dsmem[];
    const uint32_t sbase = smem_u32(dsmem);

    const int tid  = threadIdx.x;
    const int wid  = tid >> 5;
    const int lane = tid & 31;
    const int wm   = wid >> 1;
    const int wn   = wid & 1;

    const int nch = K >> 6;
    const char* srcA = (const char*)Ap + (size_t)blockIdx.y * nch * TB;
    const char* srcB = (const char*)Bp + (size_t)blockIdx.x * nch * TB;

    float acc[2][8][4];
#pragma unroll
    for (int i = 0; i < 2; i++)
#pragma unroll
        for (int j = 0; j < 8; j++)
#pragma unroll
            for (int q = 0; q < 4; q++) acc[i][j][q] = 0.f;

    copy_stage(sbase, srcA, srcB, tid);
    CP_COMMIT();

    for (int ch = 0; ch < nch; ++ch) {
        if (ch + 1 < nch) {
            copy_stage(sbase + ((ch + 1) & 1) * STAGE_BYTES,
                       srcA + (size_t)(ch + 1) * TB, srcB + (size_t)(ch + 1) * TB, tid);
            CP_COMMIT();
            CP_WAIT(1);
        } else {
            CP_WAIT(0);
        }
        __syncthreads();

        const uint32_t sA = sbase + (ch & 1) * STAGE_BYTES;
        mma_chunk(sA, sA + TB, wm, wn, lane, acc);
        __syncthreads();
    }

    const int m0 = blockIdx.y * 128 + wm * 32 + (lane >> 2);
    const int n0 = blockIdx.x * 128 + wn * 64 + (lane & 3) * 2;
    const int nkc = N >> 6;

#pragma unroll
    for (int im = 0; im < 2; im++) {
#pragma unroll
        for (int half = 0; half < 2; half++) {
            const int row = m0 + im * 16 + half * 8;
            float* crow = (OUT == 0) ? (C + (size_t)row * N) : nullptr;
            const float* rrow = (EPI == 4) ? (resid + (size_t)row * N) : nullptr;
#pragma unroll
            for (int jn = 0; jn < 8; jn++) {
                const int col = n0 + jn * 8;
                float v0 = acc[im][jn][half * 2 + 0] + bias[col];
                float v1 = acc[im][jn][half * 2 + 1] + bias[col + 1];
                if (EPI == 1) { v0 = gelu_exact(v0); v1 = gelu_exact(v1); }
                else if (EPI == 4) { v0 += rrow[col]; v1 += rrow[col + 1]; }

                if (OUT == 0) {
                    *(float2*)(crow + col) = make_float2(v0, v1);
                } else {
                    __half h0 = __float2half(v0);
                    __half h1 = __float2half(v1);
                    uint32_t hp = ((uint32_t)__half_as_ushort(h1) << 16) | __half_as_ushort(h0);
                    if (OUT == 1) {
                        size_t blk = (size_t)(row >> 7) * nkc + (col >> 6);
                        uint32_t sw = sw128((uint32_t)((row & 127) * 128 + (col & 63) * 2));
                        *(uint32_t*)((char*)Hout + blk * 16384 + sw) = hp;
                    } else {
                        *(uint32_t*)(Hout + (size_t)row * N + col) = hp;
                    }
                }
            }
        }
    }
}

// ---------------------------------------------------------------------------
// Parallel scan (fp16 proj inputs, fp32 x, fp32 accumulation)
// ---------------------------------------------------------------------------
__device__ __forceinline__ float2 ldh2(const __half* p) {
    return __half22float2(*(const __half2*)p);
}

__global__ __launch_bounds__(256)
void scan_sum1(const float* __restrict__ iscale)
{
    const int chunk = blockIdx.x, b = blockIdx.y;
    const int d0 = threadIdx.x * 2;
    float2 is2 = *(const float2*)(iscale + d0);
    const float i0 = fabsf(is2.x), i1 = fabsf(is2.y);

    size_t idx = ((size_t)b * Sz + (size_t)chunk * SLEN) * Dz + d0;
    float sp0 = 0.f, sp1 = 0.f, sm0 = 0.f, sm1 = 0.f;
#pragma unroll 4
    for (int s = 0; s < SLEN; ++s) {
        float2 g = ldh2(g_gate + idx);
        float2 o = ldh2(g_omega + idx);
        float2 m = ldh2(g_mag + idx);
        sp0 += g.x * o.x * i0;  sp1 += g.y * o.y * i1;
        sm0 += m.x;             sm1 += m.y;
        idx += Dz;
    }
    int ch = b * Dz + d0;
    *(float2*)&g_sphi[chunk * NCHAN + ch] = make_float2(sp0, sp1);
    *(float2*)&g_sm  [chunk * NCHAN + ch] = make_float2(sm0, sm1);
}

__global__ void scan_pfx1()
{
    int ch = blockIdx.x * blockDim.x + threadIdx.x;
    if (ch >= NCHAN) return;
    float rp = 0.f, rm = 0.f;
    for (int c = 0; c < SCH; ++c) {
        int i = c * NCHAN + ch;
        float tp = g_sphi[i]; g_sphi[i] = rp; rp += tp;
        float tm = g_sm[i];   g_sm[i]   = rm; rm += tm;
    }
}

__global__ __launch_bounds__(256)
void scan_sum2(const float* __restrict__ x, const float* __restrict__ iscale)
{
    const int chunk = blockIdx.x, b = blockIdx.y;
    const int d0 = threadIdx.x * 2;
    float2 is2 = *(const float2*)(iscale + d0);
    const float i0 = fabsf(is2.x), i1 = fabsf(is2.y);
    const int ch = b * Dz + d0;
    float2 phib = *(const float2*)&g_sphi[chunk * NCHAN + ch];

    size_t idx = ((size_t)b * Sz + (size_t)chunk * SLEN) * Dz + d0;
    float pc0 = 0.f, pc1 = 0.f, r0 = 0.f, r1 = 0.f, q0 = 0.f, q1 = 0.f;
#pragma unroll 4
    for (int s = 0; s < SLEN; ++s) {
        float2 g = ldh2(g_gate + idx);
        float2 o = ldh2(g_omega + idx);
        float2 m = ldh2(g_mag + idx);
        float2 xv = *(const float2*)(x + idx);
        float2 pv = ldh2(g_phii + idx);
        pc0 += g.x * o.x * i0;
        pc1 += g.y * o.y * i1;
        float c, sn;
        __sincosf(pv.x + phib.x + pc0, &sn, &c);
        float wc = m.x * xv.x;
        r0 += wc * c;  q0 += wc * sn;
        __sincosf(pv.y + phib.y + pc1, &sn, &c);
        wc = m.y * xv.y;
        r1 += wc * c;  q1 += wc * sn;
        idx += Dz;
    }
    *(float2*)&g_smr[chunk * NCHAN + ch] = make_float2(r0, r1);
    *(float2*)&g_smi[chunk * NCHAN + ch] = make_float2(q0, q1);
}

__global__ void scan_pfx2()
{
    int ch = blockIdx.x * blockDim.x + threadIdx.x;
    if (ch >= NCHAN) return;
    float rr = 0.f, ri = 0.f;
    for (int c = 0; c < SCH; ++c) {
        int i = c * NCHAN + ch;
        float tr = g_smr[i]; g_smr[i] = rr; rr += tr;
        float ti = g_smi[i]; g_smi[i] = ri; ri += ti;
    }
}

__device__ __forceinline__ float block_reduce_sum(float val)
{
    __shared__ float sh[8];
    int lane = threadIdx.x & 31, w = threadIdx.x >> 5;
    __syncthreads();
#pragma unroll
    for (int o = 16; o > 0; o >>= 1) val += __shfl_down_sync(0xffffffffu, val, o);
    if (lane == 0) sh[w] = val;
    __syncthreads();
    if (w == 0) {
        val = (lane < 8) ? sh[lane] : 0.f;
#pragma unroll
        for (int o = 4; o > 0; o >>= 1) val += __shfl_down_sync(0xffffffffu, val, o);
        if (lane == 0) sh[0] = val;
    }
    __syncthreads();
    return sh[0];
}

__global__ __launch_bounds__(256)
void scan_final_ln(const float* __restrict__ x, const float* __restrict__ iscale,
                   const float* __restrict__ gamma, const float* __restrict__ beta,
                   __half* __restrict__ Pctx)
{
    const int chunk = blockIdx.x, b = blockIdx.y;
    const int d0 = threadIdx.x * 2;
    float2 is2 = *(const float2*)(iscale + d0);
    const float i0 = fabsf(is2.x), i1 = fabsf(is2.y);
    const int ch = b * Dz + d0;

    float2 phib = *(const float2*)&g_sphi[chunk * NCHAN + ch];
    float2 mr   = *(const float2*)&g_smr [chunk * NCHAN + ch];
    float2 mi   = *(const float2*)&g_smi [chunk * NCHAN + ch];
    float2 cm   = *(const float2*)&g_sm  [chunk * NCHAN + ch];

    float2 gg[4], bb[4];
#pragma unroll
    for (int j = 0; j < 4; j++) {
        gg[j] = *(const float2*)(gamma + j * Dz + d0);
        bb[j] = *(const float2*)(beta  + j * Dz + d0);
    }

    int row = b * Sz + chunk * SLEN;
    size_t idx = (size_t)row * Dz + d0;
    float pc0 = 0.f, pc1 = 0.f;

    for (int s = 0; s < SLEN; ++s, ++row, idx += Dz) {
        float2 g  = ldh2(g_gate + idx);
        float2 o  = ldh2(g_omega + idx);
        float2 m  = ldh2(g_mag + idx);
        float2 xv = *(const float2*)(x + idx);
        float2 pv = ldh2(g_phii + idx);
        uint2 qq  = *(const uint2*)&g_qsc[idx];
        float2 qc0 = __half22float2(*(__half2*)&qq.x);  // (cos, sin) of qoff ch0
        float2 qc1 = __half22float2(*(__half2*)&qq.y);  // (cos, sin) of qoff ch1

        float v[2][4];
        {
            pc0 += g.x * o.x * i0;
            float phi = pv.x + phib.x + pc0;
            float c, sn; __sincosf(phi, &sn, &c);
            float wc = m.x * xv.x;
            mr.x += wc * c;  mi.x += wc * sn;  cm.x += m.x;
            float r = rsqrtf(cm.x + 1e-8f);
            float mrn = mr.x * r, min_ = mi.x * r;
            float cq = c * qc0.x - sn * qc0.y;
            float sq = sn * qc0.x + c * qc0.y;
            v[0][0] = xv.x * c;  v[0][1] = xv.x * sn;
            v[0][2] = mrn * cq + min_ * sq;  v[0][3] = min_ * cq - mrn * sq;
        }
        {
            pc1 += g.y * o.y * i1;
            float phi = pv.y + phib.y + pc1;
            float c, sn; __sincosf(phi, &sn, &c);
            float wc = m.y * xv.y;
            mr.y += wc * c;  mi.y += wc * sn;  cm.y += m.y;
            float r = rsqrtf(cm.y + 1e-8f);
            float mrn = mr.y * r, min_ = mi.y * r;
            float cq = c * qc1.x - sn * qc1.y;
            float sq = sn * qc1.x + c * qc1.y;
            v[1][0] = xv.y * c;  v[1][1] = xv.y * sn;
            v[1][2] = mrn * cq + min_ * sq;  v[1][3] = min_ * cq - mrn * sq;
        }

        float part = 0.f;
#pragma unroll
        for (int j = 0; j < 4; j++) part += v[0][j] + v[1][j];
        float mean = block_reduce_sum(part) * (1.0f / (float)D4);

        float sqp = 0.f;
#pragma unroll
        for (int j = 0; j < 4; j++) {
            float a0 = v[0][j] - mean, a1 = v[1][j] - mean;
            sqp += a0 * a0 + a1 * a1;
        }
        float rstd = rsqrtf(block_reduce_sum(sqp) * (1.0f / (float)D4) + 1e-5f);

        const size_t blkrow = (size_t)(row >> 7) * (D4 >> 6);
        const uint32_t rsw = (uint32_t)((row & 127) * 128);
#pragma unroll
        for (int j = 0; j < 4; j++) {
            float y0 = (v[0][j] - mean) * rstd * gg[j].x + bb[j].x;
            float y1 = (v[1][j] - mean) * rstd * gg[j].y + bb[j].y;
            __half h0 = __float2half(y0);
            __half h1 = __float2half(y1);
            uint32_t hp = ((uint32_t)__half_as_ushort(h1) << 16) | __half_as_ushort(h0);
            const int col = j * Dz + d0;
            size_t blk = blkrow + (col >> 6);
            uint32_t sw = sw128(rsw + (uint32_t)((col & 63) * 2));
            *(uint32_t*)((char*)Pctx + blk * 16384 + sw) = hp;
        }
    }
}

// ---------------------------------------------------------------------------
// launch
// ---------------------------------------------------------------------------
static inline void* sym(const void* s) { void* p = nullptr; cudaGetSymbolAddress(&p, s); return p; }

extern "C" void kernel_launch(void* const* d_in, const int* in_sizes, int n_in,
                              void* d_out, int out_size)
{
    const float* x       = (const float*)d_in[0];
    const float* W_omega = (const float*)d_in[1];
    const float* b_omega = (const float*)d_in[2];
    const float* W_p1    = (const float*)d_in[3];
    const float* b_p1    = (const float*)d_in[4];
    const float* W_p2    = (const float*)d_in[5];
    const float* b_p2    = (const float*)d_in[6];
    const float* W_gate  = (const float*)d_in[7];
    const float* b_gate  = (const float*)d_in[8];
    const float* iscale  = (const float*)d_in[9];
    const float* W_mag   = (const float*)d_in[10];
    const float* b_mag   = (const float*)d_in[11];
    const float* W_qoff  = (const float*)d_in[12];
    const float* b_qoff  = (const float*)d_in[13];
    const float* ln_g    = (const float*)d_in[14];
    const float* ln_b    = (const float*)d_in[15];
    const float* W_o1    = (const float*)d_in[16];
    const float* b_o1    = (const float*)d_in[17];
    const float* W_o2    = (const float*)d_in[18];
    const float* b_o2    = (const float*)d_in[19];
    float* out = (float*)d_out;

    __half* p_omega = (__half*)sym(g_omega);
    __half* p_mag   = (__half*)sym(g_mag);
    __half* p_gate  = (__half*)sym(g_gate);
    __half* p_phii  = (__half*)sym(g_phii);
    uint32_t* qsc   = (uint32_t*)sym(g_qsc);

    __half* xp   = (__half*)sym(g_xp);
    __half* p1p  = (__half*)sym(g_p1p);
    __half* cxp  = (__half*)sym(g_ctxp);
    __half* hp   = (__half*)sym(g_hp);

    __half* wcat = (__half*)sym(g_wcat);
    __half* wp2  = (__half*)sym(g_wp2);
    __half* wo1  = (__half*)sym(g_wo1);
    __half* wo2  = (__half*)sym(g_wo2);

    cudaFuncSetAttribute(proj_gemm,     cudaFuncAttributeMaxDynamicSharedMemorySize, GEMM_SMEM);
    cudaFuncSetAttribute(gemm_mma<0,2>, cudaFuncAttributeMaxDynamicSharedMemorySize, GEMM_SMEM);
    cudaFuncSetAttribute(gemm_mma<1,1>, cudaFuncAttributeMaxDynamicSharedMemorySize, GEMM_SMEM);
    cudaFuncSetAttribute(gemm_mma<4,0>, cudaFuncAttributeMaxDynamicSharedMemorySize, GEMM_SMEM);

    // --- pack everything in one launch ---
    pack_all<<<10240, 256>>>(x, xp,
                             W_omega, W_mag, W_gate, W_qoff, W_p1, W_p2,
                             W_o1, W_o2,
                             wcat, wp2, wo1, wo2);

    dim3 blk(256);

    // fused projections (omega, mag, gate, qoff->sincos, p1), grid (20, 256)
    proj_gemm<<<dim3(20, Mz / 128), blk, GEMM_SMEM>>>(
        xp, wcat,
        b_omega, b_mag, b_gate, b_qoff, b_p1,
        p_omega, p_mag, p_gate, qsc, p1p);

    // p2 -> phii (fp16 row-major)
    gemm_mma<0,2><<<dim3(4, Mz / 128), blk, GEMM_SMEM>>>(
        p1p, wp2, b_p2, nullptr, p_phii, nullptr, Dz, Dz);

    // parallel scan + fused LN/pack
    dim3 sgrid(SCH, Bz);
    scan_sum1<<<sgrid, 256>>>(iscale);
    scan_pfx1<<<NCHAN / 256, 256>>>();
    scan_sum2<<<sgrid, 256>>>(x, iscale);
    scan_pfx2<<<NCHAN / 256, 256>>>();
    scan_final_ln<<<sgrid, 256>>>(x, iscale, ln_g, ln_b, cxp);

    // output MLP
    gemm_mma<1,1><<<dim3(D2 / 128, Mz / 128), blk, GEMM_SMEM>>>(
        cxp, wo1, b_o1, nullptr, hp, nullptr, D2, D4);
    gemm_mma<4,0><<<dim3(Dz / 128, Mz / 128), blk, GEMM_SMEM>>>(
        hp, wo2, b_o2, out, nullptr, x, Dz, D2);
}

// round 16
// speedup vs baseline: 1.0740x; 1.0438x over previous
#include <cuda_runtime.h>
#include <cuda_fp16.h>
#include <math.h>
#include <stdint.h>

#define Bz 8
#define Sz 4096
#define Dz 512
#define Mz (Bz * Sz)          // 32768 rows
#define D4 (4 * Dz)           // 2048
#define D2 (2 * Dz)           // 1024

#define SCH 64                // scan chunks
#define SLEN (Sz / SCH)       // 64 steps per chunk
#define NCHAN (Bz * Dz)       // 4096 channels

// ---------------------------------------------------------------------------
// Scratch (static device globals; no allocation)
// ---------------------------------------------------------------------------
// scan inputs, fp16 row-major [Mz, Dz]
__device__ __half g_omega[(size_t)Mz * Dz];
__device__ __half g_mag  [(size_t)Mz * Dz];
__device__ __half g_gate [(size_t)Mz * Dz];
__device__ __half g_qoff [(size_t)Mz * Dz];
__device__ __half g_phii [(size_t)Mz * Dz];

// scan chunk statistics [chunk][channel]
__device__ float g_sphi[SCH * NCHAN];
__device__ float g_sm  [SCH * NCHAN];
__device__ float g_smr [SCH * NCHAN];   // z_r (pre-rotation), then prefix
__device__ float g_smi [SCH * NCHAN];   // z_i

// packed fp16 activations (SW128 tile-blocked)
__device__ __half g_xp  [(size_t)Mz * Dz];
__device__ __half g_p1p [(size_t)Mz * Dz];
__device__ __half g_ctxp[(size_t)Mz * D4];
__device__ __half g_hp  [(size_t)Mz * D2];

// fp16 weights (transposed to [N,K], SW128 tile-blocked)
__device__ __half g_wcat[5 * Dz * Dz];          // [omega|mag|gate|qoff|p1]
__device__ __half g_wp2[Dz * Dz];
__device__ __half g_wo1[(size_t)D4 * D2];
__device__ __half g_wo2[D2 * Dz];

// ---------------------------------------------------------------------------
// PTX helpers
// ---------------------------------------------------------------------------
__device__ __forceinline__ uint32_t smem_u32(const void* p) {
    uint32_t a;
    asm("{ .reg .u64 t; cvta.to.shared.u64 t, %1; cvt.u32.u64 %0, t; }" : "=r"(a) : "l"(p));
    return a;
}

__device__ __forceinline__ void cp16(uint32_t dst, const void* src) {
    asm volatile("cp.async.cg.shared.global [%0], [%1], 16;" :: "r"(dst), "l"(src));
}
#define CP_COMMIT() asm volatile("cp.async.commit_group;" ::: "memory")
#define CP_WAIT(n)  asm volatile("cp.async.wait_group %0;" :: "n"(n) : "memory")

__device__ __forceinline__ void ldsm4(uint32_t* r, uint32_t addr) {
    asm volatile("ldmatrix.sync.aligned.m8n8.x4.shared.b16 {%0,%1,%2,%3}, [%4];"
                 : "=r"(r[0]), "=r"(r[1]), "=r"(r[2]), "=r"(r[3]) : "r"(addr));
}

__device__ __forceinline__ void mma16816(float* d, const uint32_t* a, uint32_t b0, uint32_t b1) {
    asm volatile(
        "mma.sync.aligned.m16n8k16.row.col.f32.f16.f16.f32 "
        "{%0,%1,%2,%3}, {%4,%5,%6,%7}, {%8,%9}, {%0,%1,%2,%3};"
        : "+f"(d[0]), "+f"(d[1]), "+f"(d[2]), "+f"(d[3])
        : "r"(a[0]), "r"(a[1]), "r"(a[2]), "r"(a[3]), "r"(b0), "r"(b1));
}

__device__ __forceinline__ uint32_t sw128(uint32_t b) { return b ^ ((b >> 3) & 0x70); }

// ---------------------------------------------------------------------------
// Fused packing: one launch covers all weights + x.
// ---------------------------------------------------------------------------
__device__ __forceinline__ void pack_w_do(const float* __restrict__ W,
                                          __half* __restrict__ P,
                                          int K, int N, long idx)
{
    int n  = (int)(idx % N);
    int k  = (int)(idx / N) << 3;
    __align__(16) __half h[8];
#pragma unroll
    for (int i = 0; i < 8; i++) h[i] = __float2half(W[(size_t)(k + i) * N + n]);
    int nt = n >> 7, rn = n & 127, ch = k >> 6, c = k & 63;
    size_t blk = (size_t)nt * (K >> 6) + ch;
    uint32_t sw = sw128((uint32_t)(rn * 128 + c * 2));
    *(uint4*)((char*)P + blk * 16384 + sw) = *(const uint4*)h;
}

__device__ __forceinline__ void pack_a_do(const float* __restrict__ A,
                                          __half* __restrict__ P,
                                          int K, long idx)
{
    int kk8 = K >> 3;
    int row = (int)(idx / kk8);
    int k   = (int)(idx % kk8) << 3;
    const float4* p = (const float4*)(A + (size_t)row * K + k);
    float4 a = p[0], b = p[1];
    float v[8] = {a.x, a.y, a.z, a.w, b.x, b.y, b.z, b.w};
    __align__(16) __half h[8];
#pragma unroll
    for (int i = 0; i < 8; i++) h[i] = __float2half(v[i]);
    int mt = row >> 7, r = row & 127, ch = k >> 6, c = k & 63;
    size_t blk = (size_t)mt * (K >> 6) + ch;
    uint32_t sw = sw128((uint32_t)(r * 128 + c * 2));
    *(uint4*)((char*)P + blk * 16384 + sw) = *(const uint4*)h;
}

__global__ __launch_bounds__(256)
void pack_all(const float* __restrict__ x, __half* __restrict__ xp,
              const float* __restrict__ w0, const float* __restrict__ w1,
              const float* __restrict__ w2, const float* __restrict__ w3,
              const float* __restrict__ w4, const float* __restrict__ w5,
              const float* __restrict__ wo1s, const float* __restrict__ wo2s,
              __half* __restrict__ wcat, __half* __restrict__ wp2d,
              __half* __restrict__ wo1d, __half* __restrict__ wo2d)
{
    const int bid = blockIdx.x;
    if (bid < 768) {
        const int job = bid >> 7;                 // 0..5
        long idx = (long)(bid & 127) * 256 + threadIdx.x;
        const float* src = (job == 0) ? w0 : (job == 1) ? w1 : (job == 2) ? w2 :
                           (job == 3) ? w3 : (job == 4) ? w4 : w5;
        __half* dst = (job < 5) ? (wcat + (size_t)job * Dz * Dz) : wp2d;
        pack_w_do(src, dst, Dz, Dz, idx);
    } else if (bid < 1792) {
        long idx = (long)(bid - 768) * 256 + threadIdx.x;
        pack_w_do(wo1s, wo1d, D4, D2, idx);
    } else if (bid < 2048) {
        long idx = (long)(bid - 1792) * 256 + threadIdx.x;
        pack_w_do(wo2s, wo2d, D2, Dz, idx);
    } else {
        long idx = (long)(bid - 2048) * 256 + threadIdx.x;
        pack_a_do(x, xp, Dz, idx);
    }
}

// ---------------------------------------------------------------------------
// MMA core: BM=128, BN=128, BK=64, 256 threads (8 warps: 4 wm x 2 wn),
// warp tile 32x64. Stage = A + B = 32KB. 2-stage pipeline, 2 CTAs/SM. (R12)
// ---------------------------------------------------------------------------
#define TB 16384
#define STAGE_BYTES (2 * TB)
#define GEMM_SMEM   (2 * STAGE_BYTES)   // 64KB -> 2 CTAs/SM

__device__ __forceinline__ void mma_chunk(uint32_t sA, uint32_t sB,
                                          int wm, int wn, int lane,
                                          float acc[2][8][4])
{
    const int a_row = lane & 15;
    const int a_kb  = (lane >> 4) * 16;
#pragma unroll
    for (int k16 = 0; k16 < 4; ++k16) {
        const int kb = k16 * 32 + a_kb;
        uint32_t ah[2][4], bh[4][4];
#pragma unroll
        for (int im = 0; im < 2; im++) {
            uint32_t b = (uint32_t)((wm * 32 + im * 16 + a_row) * 128 + kb);
            ldsm4(ah[im], sA + sw128(b));
        }
#pragma unroll
        for (int j2 = 0; j2 < 4; j2++) {
            uint32_t b = (uint32_t)((wn * 64 + j2 * 16 + a_row) * 128 + kb);
            ldsm4(bh[j2], sB + sw128(b));
        }
#pragma unroll
        for (int im = 0; im < 2; im++)
#pragma unroll
            for (int jn = 0; jn < 8; jn++) {
                const int j2 = jn >> 1, jo = jn & 1;
                mma16816(acc[im][jn], ah[im], bh[j2][jo], bh[j2][2 + jo]);
            }
    }
}

__device__ __forceinline__ float gelu_exact(float v) {
    return 0.5f * v * (1.0f + erff(v * 0.70710678118654752f));
}

__device__ __forceinline__ void copy_stage(uint32_t sdst,
                                           const char* A, const char* B, int tid)
{
#pragma unroll
    for (int j = 0; j < 4; j++) {
        uint32_t o = (uint32_t)tid * 16 + j * 4096;
        cp16(sdst + o,      A + o);
        cp16(sdst + TB + o, B + o);
    }
}

// ---------------------------------------------------------------------------
// Fused projection GEMM: grid (20, 256). group = bx>>2 (0..4), n-tile = bx&3.
// group: 0 omega, 1 mag(sig5), 2 gate(sig), 3 qoff -> fp16 row-major out,
//        4 p1(gelu) -> packed fp16
// ---------------------------------------------------------------------------
__global__ __launch_bounds__(256, 2)
void proj_gemm(const __half* __restrict__ Ap, const __half* __restrict__ W,
               const float* __restrict__ b_om, const float* __restrict__ b_mg,
               const float* __restrict__ b_gt, const float* __restrict__ b_qo,
               const float* __restrict__ b_p1,
               __half* __restrict__ c_om, __half* __restrict__ c_mg,
               __half* __restrict__ c_gt, __half* __restrict__ c_qo,
               __half* __restrict__ p1p)
{
    extern __shared__ __align__(1024) char dsmem[];
    const uint32_t sbase = smem_u32(dsmem);

    const int tid  = threadIdx.x;
    const int wid  = tid >> 5;
    const int lane = tid & 31;
    const int wm   = wid >> 1;      // 0..3 (32 rows each)
    const int wn   = wid & 1;       // 0..1 (64 cols each)

    const int group = blockIdx.x >> 2;
    const int ntile = blockIdx.x & 3;

    const int nch = 8;  // K=512
    const char* srcA = (const char*)Ap + (size_t)blockIdx.y * nch * TB;
    const char* srcB = (const char*)W + ((size_t)group * 4 + ntile) * nch * TB;

    float acc[2][8][4];
#pragma unroll
    for (int i = 0; i < 2; i++)
#pragma unroll
        for (int j = 0; j < 8; j++)
#pragma unroll
            for (int q = 0; q < 4; q++) acc[i][j][q] = 0.f;

    copy_stage(sbase, srcA, srcB, tid);
    CP_COMMIT();

    for (int ch = 0; ch < nch; ++ch) {
        if (ch + 1 < nch) {
            copy_stage(sbase + ((ch + 1) & 1) * STAGE_BYTES,
                       srcA + (size_t)(ch + 1) * TB, srcB + (size_t)(ch + 1) * TB, tid);
            CP_COMMIT();
            CP_WAIT(1);
        } else {
            CP_WAIT(0);
        }
        __syncthreads();

        const uint32_t sA = sbase + (ch & 1) * STAGE_BYTES;
        mma_chunk(sA, sA + TB, wm, wn, lane, acc);
        __syncthreads();
    }

    // ---------------- epilogue ----------------
    const float* bias = (group == 0) ? b_om : (group == 1) ? b_mg :
                        (group == 2) ? b_gt : (group == 3) ? b_qo : b_p1;
    __half* cout = (group == 0) ? c_om : (group == 1) ? c_mg :
                   (group == 2) ? c_gt : c_qo;

    const int m0  = blockIdx.y * 128 + wm * 32 + (lane >> 2);
    const int nl0 = ntile * 128 + wn * 64 + (lane & 3) * 2;

#pragma unroll
    for (int im = 0; im < 2; im++) {
#pragma unroll
        for (int half = 0; half < 2; half++) {
            const int row = m0 + im * 16 + half * 8;
#pragma unroll
            for (int jn = 0; jn < 8; jn++) {
                const int col = nl0 + jn * 8;   // 0..511 within group
                float v0 = acc[im][jn][half * 2 + 0] + bias[col];
                float v1 = acc[im][jn][half * 2 + 1] + bias[col + 1];
                if (group == 1) { v0 = 5.f / (1.f + expf(-v0)); v1 = 5.f / (1.f + expf(-v1)); }
                else if (group == 2) { v0 = 1.f / (1.f + expf(-v0)); v1 = 1.f / (1.f + expf(-v1)); }
                else if (group == 4) { v0 = gelu_exact(v0); v1 = gelu_exact(v1); }

                __half h0 = __float2half(v0);
                __half h1 = __float2half(v1);
                uint32_t hp = ((uint32_t)__half_as_ushort(h1) << 16) | __half_as_ushort(h0);
                if (group == 4) {
                    size_t blk = (size_t)(row >> 7) * 8 + (col >> 6);
                    uint32_t sw = sw128((uint32_t)((row & 127) * 128 + (col & 63) * 2));
                    *(uint32_t*)((char*)p1p + blk * 16384 + sw) = hp;
                } else {
                    *(uint32_t*)(cout + (size_t)row * Dz + col) = hp;
                }
            }
        }
    }
}

// ---------------------------------------------------------------------------
// generic GEMM: EPI 0 none, 1 gelu, 4 +resid.
// OUT: 0 = fp32 C, 1 = packed fp16 (SW128 blocked), 2 = fp16 row-major
// grid (N/128, M/128)
// ---------------------------------------------------------------------------
template <int EPI, int OUT>
__global__ __launch_bounds__(256, 2)
void gemm_mma(const __half* __restrict__ Ap, const __half* __restrict__ Bp,
              const float* __restrict__ bias, float* __restrict__ C,
              __half* __restrict__ Hout,
              const float* __restrict__ resid, int N, int K)
{
    extern __shared__ __align__(1024) char dsmem[];
    const uint32_t sbase = smem_u32(dsmem);

    const int tid  = threadIdx.x;
    const int wid  = tid >> 5;
    const int lane = tid & 31;
    const int wm   = wid >> 1;
    const int wn   = wid & 1;

    const int nch = K >> 6;
    const char* srcA = (const char*)Ap + (size_t)blockIdx.y * nch * TB;
    const char* srcB = (const char*)Bp + (size_t)blockIdx.x * nch * TB;

    float acc[2][8][4];
#pragma unroll
    for (int i = 0; i < 2; i++)
#pragma unroll
        for (int j = 0; j < 8; j++)
#pragma unroll
            for (int q = 0; q < 4; q++) acc[i][j][q] = 0.f;

    copy_stage(sbase, srcA, srcB, tid);
    CP_COMMIT();

    for (int ch = 0; ch < nch; ++ch) {
        if (ch + 1 < nch) {
            copy_stage(sbase + ((ch + 1) & 1) * STAGE_BYTES,
                       srcA + (size_t)(ch + 1) * TB, srcB + (size_t)(ch + 1) * TB, tid);
            CP_COMMIT();
            CP_WAIT(1);
        } else {
            CP_WAIT(0);
        }
        __syncthreads();

        const uint32_t sA = sbase + (ch & 1) * STAGE_BYTES;
        mma_chunk(sA, sA + TB, wm, wn, lane, acc);
        __syncthreads();
    }

    const int m0 = blockIdx.y * 128 + wm * 32 + (lane >> 2);
    const int n0 = blockIdx.x * 128 + wn * 64 + (lane & 3) * 2;
    const int nkc = N >> 6;

#pragma unroll
    for (int im = 0; im < 2; im++) {
#pragma unroll
        for (int half = 0; half < 2; half++) {
            const int row = m0 + im * 16 + half * 8;
            float* crow = (OUT == 0) ? (C + (size_t)row * N) : nullptr;
            const float* rrow = (EPI == 4) ? (resid + (size_t)row * N) : nullptr;
#pragma unroll
            for (int jn = 0; jn < 8; jn++) {
                const int col = n0 + jn * 8;
                float v0 = acc[im][jn][half * 2 + 0] + bias[col];
                float v1 = acc[im][jn][half * 2 + 1] + bias[col + 1];
                if (EPI == 1) { v0 = gelu_exact(v0); v1 = gelu_exact(v1); }
                else if (EPI == 4) { v0 += rrow[col]; v1 += rrow[col + 1]; }

                if (OUT == 0) {
                    *(float2*)(crow + col) = make_float2(v0, v1);
                } else {
                    __half h0 = __float2half(v0);
                    __half h1 = __float2half(v1);
                    uint32_t hp = ((uint32_t)__half_as_ushort(h1) << 16) | __half_as_ushort(h0);
                    if (OUT == 1) {
                        size_t blk = (size_t)(row >> 7) * nkc + (col >> 6);
                        uint32_t sw = sw128((uint32_t)((row & 127) * 128 + (col & 63) * 2));
                        *(uint32_t*)((char*)Hout + blk * 16384 + sw) = hp;
                    } else {
                        *(uint32_t*)(Hout + (size_t)row * N + col) = hp;
                    }
                }
            }
        }
    }
}

// ---------------------------------------------------------------------------
// Parallel scan, rotate-decomposed:
// sum1 computes per-chunk: sp (phi increments), sm (mag), and z = sum of
// wc * e^{i(phi_init + pc_local)} (NO cross-chunk term needed).
// pfx rotates z by the phi prefix and computes all exclusive prefixes.
// ---------------------------------------------------------------------------
__device__ __forceinline__ float2 ldh2(const __half* p) {
    return __half22float2(*(const __half2*)p);
}

__global__ __launch_bounds__(256)
void scan_sum1(const float* __restrict__ x, const float* __restrict__ iscale)
{
    const int chunk = blockIdx.x, b = blockIdx.y;
    const int d0 = threadIdx.x * 2;
    float2 is2 = *(const float2*)(iscale + d0);
    const float i0 = fabsf(is2.x), i1 = fabsf(is2.y);

    size_t idx = ((size_t)b * Sz + (size_t)chunk * SLEN) * Dz + d0;
    float sp0 = 0.f, sp1 = 0.f, sm0 = 0.f, sm1 = 0.f;
    float zr0 = 0.f, zi0 = 0.f, zr1 = 0.f, zi1 = 0.f;
#pragma unroll 2
    for (int s = 0; s < SLEN; ++s) {
        float2 g = ldh2(g_gate + idx);
        float2 o = ldh2(g_omega + idx);
        float2 m = ldh2(g_mag + idx);
        float2 xv = *(const float2*)(x + idx);
        float2 pv = ldh2(g_phii + idx);
        sp0 += g.x * o.x * i0;
        sp1 += g.y * o.y * i1;
        sm0 += m.x;  sm1 += m.y;
        float c, sn;
        __sincosf(pv.x + sp0, &sn, &c);
        float wc = m.x * xv.x;
        zr0 += wc * c;  zi0 += wc * sn;
        __sincosf(pv.y + sp1, &sn, &c);
        wc = m.y * xv.y;
        zr1 += wc * c;  zi1 += wc * sn;
        idx += Dz;
    }
    int ch = b * Dz + d0;
    *(float2*)&g_sphi[chunk * NCHAN + ch] = make_float2(sp0, sp1);
    *(float2*)&g_sm  [chunk * NCHAN + ch] = make_float2(sm0, sm1);
    *(float2*)&g_smr [chunk * NCHAN + ch] = make_float2(zr0, zr1);
    *(float2*)&g_smi [chunk * NCHAN + ch] = make_float2(zi0, zi1);
}

// single prefix pass: phi prefix, rotate z, prefix mr/mi/m
__global__ void scan_pfx()
{
    int ch = blockIdx.x * blockDim.x + threadIdx.x;
    if (ch >= NCHAN) return;
    float rp = 0.f, rm = 0.f, rr = 0.f, ri = 0.f;
    for (int c = 0; c < SCH; ++c) {
        int i = c * NCHAN + ch;
        float tp = g_sphi[i];
        float tm = g_sm[i];
        float zr = g_smr[i];
        float zi = g_smi[i];
        g_sphi[i] = rp;
        g_sm[i]   = rm;
        g_smr[i]  = rr;
        g_smi[i]  = ri;
        // rotate chunk-local z by phib = rp
        float cb, sb;
        __sincosf(rp, &sb, &cb);
        rr += zr * cb - zi * sb;
        ri += zr * sb + zi * cb;
        rp += tp;
        rm += tm;
    }
}

__device__ __forceinline__ float block_reduce_sum(float val)
{
    __shared__ float sh[8];
    int lane = threadIdx.x & 31, w = threadIdx.x >> 5;
    __syncthreads();
#pragma unroll
    for (int o = 16; o > 0; o >>= 1) val += __shfl_down_sync(0xffffffffu, val, o);
    if (lane == 0) sh[w] = val;
    __syncthreads();
    if (w == 0) {
        val = (lane < 8) ? sh[lane] : 0.f;
#pragma unroll
        for (int o = 4; o > 0; o >>= 1) val += __shfl_down_sync(0xffffffffu, val, o);
        if (lane == 0) sh[0] = val;
    }
    __syncthreads();
    return sh[0];
}

__global__ __launch_bounds__(256)
void scan_final_ln(const float* __restrict__ x, const float* __restrict__ iscale,
                   const float* __restrict__ gamma, const float* __restrict__ beta,
                   __half* __restrict__ Pctx)
{
    const int chunk = blockIdx.x, b = blockIdx.y;
    const int d0 = threadIdx.x * 2;
    float2 is2 = *(const float2*)(iscale + d0);
    const float i0 = fabsf(is2.x), i1 = fabsf(is2.y);
    const int ch = b * Dz + d0;

    float2 phib = *(const float2*)&g_sphi[chunk * NCHAN + ch];
    float2 mr   = *(const float2*)&g_smr [chunk * NCHAN + ch];
    float2 mi   = *(const float2*)&g_smi [chunk * NCHAN + ch];
    float2 cm   = *(const float2*)&g_sm  [chunk * NCHAN + ch];

    float2 gg[4], bb[4];
#pragma unroll
    for (int j = 0; j < 4; j++) {
        gg[j] = *(const float2*)(gamma + j * Dz + d0);
        bb[j] = *(const float2*)(beta  + j * Dz + d0);
    }

    int row = b * Sz + chunk * SLEN;
    size_t idx = (size_t)row * Dz + d0;
    float pc0 = 0.f, pc1 = 0.f;

    for (int s = 0; s < SLEN; ++s, ++row, idx += Dz) {
        float2 g  = ldh2(g_gate + idx);
        float2 o  = ldh2(g_omega + idx);
        float2 m  = ldh2(g_mag + idx);
        float2 xv = *(const float2*)(x + idx);
        float2 pv = ldh2(g_phii + idx);
        float2 qv = ldh2(g_qoff + idx);

        float v[2][4];
        {
            pc0 += g.x * o.x * i0;
            float phi = pv.x + phib.x + pc0;
            float c, sn; __sincosf(phi, &sn, &c);
            float wc = m.x * xv.x;
            mr.x += wc * c;  mi.x += wc * sn;  cm.x += m.x;
            float r = rsqrtf(cm.x + 1e-8f);
            float mrn = mr.x * r, min_ = mi.x * r;
            float cq, sq; __sincosf(phi + qv.x, &sq, &cq);
            v[0][0] = xv.x * c;  v[0][1] = xv.x * sn;
            v[0][2] = mrn * cq + min_ * sq;  v[0][3] = min_ * cq - mrn * sq;
        }
        {
            pc1 += g.y * o.y * i1;
            float phi = pv.y + phib.y + pc1;
            float c, sn; __sincosf(phi, &sn, &c);
            float wc = m.y * xv.y;
            mr.y += wc * c;  mi.y += wc * sn;  cm.y += m.y;
            float r = rsqrtf(cm.y + 1e-8f);
            float mrn = mr.y * r, min_ = mi.y * r;
            float cq, sq; __sincosf(phi + qv.y, &sq, &cq);
            v[1][0] = xv.y * c;  v[1][1] = xv.y * sn;
            v[1][2] = mrn * cq + min_ * sq;  v[1][3] = min_ * cq - mrn * sq;
        }

        float part = 0.f;
#pragma unroll
        for (int j = 0; j < 4; j++) part += v[0][j] + v[1][j];
        float mean = block_reduce_sum(part) * (1.0f / (float)D4);

        float sqp = 0.f;
#pragma unroll
        for (int j = 0; j < 4; j++) {
            float a0 = v[0][j] - mean, a1 = v[1][j] - mean;
            sqp += a0 * a0 + a1 * a1;
        }
        float rstd = rsqrtf(block_reduce_sum(sqp) * (1.0f / (float)D4) + 1e-5f);

        const size_t blkrow = (size_t)(row >> 7) * (D4 >> 6);
        const uint32_t rsw = (uint32_t)((row & 127) * 128);
#pragma unroll
        for (int j = 0; j < 4; j++) {
            float y0 = (v[0][j] - mean) * rstd * gg[j].x + bb[j].x;
            float y1 = (v[1][j] - mean) * rstd * gg[j].y + bb[j].y;
            __half h0 = __float2half(y0);
            __half h1 = __float2half(y1);
            uint32_t hp = ((uint32_t)__half_as_ushort(h1) << 16) | __half_as_ushort(h0);
            const int col = j * Dz + d0;
            size_t blk = blkrow + (col >> 6);
            uint32_t sw = sw128(rsw + (uint32_t)((col & 63) * 2));
            *(uint32_t*)((char*)Pctx + blk * 16384 + sw) = hp;
        }
    }
}

// ---------------------------------------------------------------------------
// launch
// ---------------------------------------------------------------------------
static inline void* sym(const void* s) { void* p = nullptr; cudaGetSymbolAddress(&p, s); return p; }

extern "C" void kernel_launch(void* const* d_in, const int* in_sizes, int n_in,
                              void* d_out, int out_size)
{
    const float* x       = (const float*)d_in[0];
    const float* W_omega = (const float*)d_in[1];
    const float* b_omega = (const float*)d_in[2];
    const float* W_p1    = (const float*)d_in[3];
    const float* b_p1    = (const float*)d_in[4];
    const float* W_p2    = (const float*)d_in[5];
    const float* b_p2    = (const float*)d_in[6];
    const float* W_gate  = (const float*)d_in[7];
    const float* b_gate  = (const float*)d_in[8];
    const float* iscale  = (const float*)d_in[9];
    const float* W_mag   = (const float*)d_in[10];
    const float* b_mag   = (const float*)d_in[11];
    const float* W_qoff  = (const float*)d_in[12];
    const float* b_qoff  = (const float*)d_in[13];
    const float* ln_g    = (const float*)d_in[14];
    const float* ln_b    = (const float*)d_in[15];
    const float* W_o1    = (const float*)d_in[16];
    const float* b_o1    = (const float*)d_in[17];
    const float* W_o2    = (const float*)d_in[18];
    const float* b_o2    = (const float*)d_in[19];
    float* out = (float*)d_out;

    __half* p_omega = (__half*)sym(g_omega);
    __half* p_mag   = (__half*)sym(g_mag);
    __half* p_gate  = (__half*)sym(g_gate);
    __half* p_qoff  = (__half*)sym(g_qoff);
    __half* p_phii  = (__half*)sym(g_phii);

    __half* xp   = (__half*)sym(g_xp);
    __half* p1p  = (__half*)sym(g_p1p);
    __half* cxp  = (__half*)sym(g_ctxp);
    __half* hp   = (__half*)sym(g_hp);

    __half* wcat = (__half*)sym(g_wcat);
    __half* wp2  = (__half*)sym(g_wp2);
    __half* wo1  = (__half*)sym(g_wo1);
    __half* wo2  = (__half*)sym(g_wo2);

    cudaFuncSetAttribute(proj_gemm,     cudaFuncAttributeMaxDynamicSharedMemorySize, GEMM_SMEM);
    cudaFuncSetAttribute(gemm_mma<0,2>, cudaFuncAttributeMaxDynamicSharedMemorySize, GEMM_SMEM);
    cudaFuncSetAttribute(gemm_mma<1,1>, cudaFuncAttributeMaxDynamicSharedMemorySize, GEMM_SMEM);
    cudaFuncSetAttribute(gemm_mma<4,0>, cudaFuncAttributeMaxDynamicSharedMemorySize, GEMM_SMEM);

    // --- pack everything in one launch ---
    pack_all<<<10240, 256>>>(x, xp,
                             W_omega, W_mag, W_gate, W_qoff, W_p1, W_p2,
                             W_o1, W_o2,
                             wcat, wp2, wo1, wo2);

    dim3 blk(256);

    // fused projections (omega, mag, gate, qoff, p1), grid (20, 256)
    proj_gemm<<<dim3(20, Mz / 128), blk, GEMM_SMEM>>>(
        xp, wcat,
        b_omega, b_mag, b_gate, b_qoff, b_p1,
        p_omega, p_mag, p_gate, p_qoff, p1p);

    // p2 -> phii (fp16 row-major)
    gemm_mma<0,2><<<dim3(4, Mz / 128), blk, GEMM_SMEM>>>(
        p1p, wp2, b_p2, nullptr, p_phii, nullptr, Dz, Dz);

    // parallel scan (rotate-decomposed) + fused LN/pack: 3 launches
    dim3 sgrid(SCH, Bz);
    scan_sum1<<<sgrid, 256>>>(x, iscale);
    scan_pfx<<<NCHAN / 256, 256>>>();
    scan_final_ln<<<sgrid, 256>>>(x, iscale, ln_g, ln_b, cxp);

    // output MLP
    gemm_mma<1,1><<<dim3(D2 / 128, Mz / 128), blk, GEMM_SMEM>>>(
        cxp, wo1, b_o1, nullptr, hp, nullptr, D2, D4);
    gemm_mma<4,0><<<dim3(Dz / 128, Mz / 128), blk, GEMM_SMEM>>>(
        hp, wo2, b_o2, out, nullptr, x, Dz, D2);
}